// round 8
// baseline (speedup 1.0000x reference)
#include <cuda_runtime.h>
#include <cuda_bf16.h>
#include <cstdint>
#include <cstddef>

#define BATCH 2
#define DIM 128
#define CIN 64
#define COUT 64
#define HH 96
#define WW 96
#define HW (HH*WW)           // 9216
#define HEADS 8
#define CH 16
#define DEPTH 4
#define NIDX (BATCH*HH)      // 192 (b,y) slots for bn partials

// ---------------- scratch (device globals) ----------------
__device__ __align__(16) float g_t  [BATCH*DIM*HW];   // conv out (fp32, pre-BN)
__device__ __align__(16) float g_bn [BATCH*DIM*HW];   // bn+relu out (fp32 residual)
__device__ __align__(16) float g_qkv[BATCH*3*DIM*HW];
__device__ __align__(16) uint2 g_hsp[BATCH*64*HW];    // split h   (conv / out-proj B)
__device__ __align__(16) uint2 g_qsp[BATCH*64*HW];    // split bn  (qkv B)
__device__ __align__(16) uint2 g_asp[BATCH*64*HW];    // split att (fc B)
__device__ float g_ps[DIM*NIDX];
__device__ float g_pq[DIM*NIDX];

// Pre-fragmented A weights: per chunk (64m x 16k tile):
// [cid][sel(2: hi/lo)][mg(4: m16 group)][lane(32)] -> uint4 {a0,a1,a2,a3}
// word j of lane l: row = mg*16 + (l>>2) + ((j&1)<<3), k2 = (l&3) + ((j>>1)<<2)
// cid map: conv d*144+(tap*8+kc)*2+mblk (0..575) | qkv 576+(d*6+mt)*8+kc (..767)
//          fc 768+(d*2+mblk)*8+kc (..831) | wi 832+mblk*4+kc (..839) | wo 840+kc (..847)
#define NCID 848
__device__ __align__(16) uint4 g_afr[(size_t)NCID*256];

__device__ __forceinline__ void split2(float x0, float x1, uint32_t& hi, uint32_t& lo)
{
    __nv_bfloat16 h0 = __float2bfloat16(x0);
    __nv_bfloat16 h1 = __float2bfloat16(x1);
    float l0f = x0 - __bfloat162float(h0);
    float l1f = x1 - __bfloat162float(h1);
    __nv_bfloat162 hh = __halves2bfloat162(h0, h1);
    __nv_bfloat162 ll = __halves2bfloat162(__float2bfloat16(l0f), __float2bfloat16(l1f));
    hi = *reinterpret_cast<uint32_t*>(&hh);
    lo = *reinterpret_cast<uint32_t*>(&ll);
}

__device__ __forceinline__ void mma_bf16(float c[4],
    uint32_t a0, uint32_t a1, uint32_t a2, uint32_t a3, uint32_t b0, uint32_t b1)
{
    asm volatile(
        "mma.sync.aligned.m16n8k16.row.col.f32.bf16.bf16.f32 "
        "{%0,%1,%2,%3}, {%4,%5,%6,%7}, {%8,%9}, {%0,%1,%2,%3};"
        : "+f"(c[0]), "+f"(c[1]), "+f"(c[2]), "+f"(c[3])
        : "r"(a0), "r"(a1), "r"(a2), "r"(a3), "r"(b0), "r"(b1));
}

// ---------------- prep: build fragment-ordered split weights ----------------
__global__ void prep_afr(const float* __restrict__ conv_w, const float* __restrict__ qkv_w,
                         const float* __restrict__ fc_w, const float* __restrict__ w_in,
                         const float* __restrict__ w_out)
{
    int i = blockIdx.x*256 + threadIdx.x;          // over NCID*128
    if (i >= NCID*128) return;
    int cid = i >> 7, r = i & 127;
    int mg = r >> 5, lane = r & 31;
    int gg = lane >> 2, tt = lane & 3;

    uint32_t hw[4], lw[4];
    #pragma unroll
    for (int j = 0; j < 4; j++) {
        int row = mg*16 + gg + ((j & 1) << 3);     // m within 64-tile
        int k2  = tt + ((j >> 1) << 2);            // k-pair within 16-k tile
        float x0 = 0.f, x1 = 0.f;
        if (cid < 576) {
            int mblk = cid & 1; int rr = cid >> 1;
            int kc = rr & 7; rr >>= 3;
            int tap = rr % 9, d = rr / 9;
            int oc = mblk*64 + row, ic = 2*(kc*8 + k2);
            size_t base = ((size_t)(d*128 + oc)*128 + ic)*9 + tap;
            x0 = conv_w[base]; x1 = conv_w[base + 9];
        } else if (cid < 768) {
            int j2 = cid - 576; int kc = j2 & 7; int rr = j2 >> 3;
            int mt = rr % 6, d = rr / 6;
            int oc = mt*64 + row, ic = 2*(kc*8 + k2);
            const float* w = &qkv_w[((size_t)d*384 + oc)*128 + ic];
            x0 = w[0]; x1 = w[1];
        } else if (cid < 832) {
            int j3 = cid - 768; int kc = j3 & 7; int rr = j3 >> 3;
            int mblk = rr & 1, d = rr >> 1;
            int oc = mblk*64 + row, ic = 2*(kc*8 + k2);
            const float* w = &fc_w[((size_t)d*128 + oc)*128 + ic];
            x0 = w[0]; x1 = w[1];
        } else if (cid < 840) {
            int j4 = cid - 832; int kc = j4 & 3; int mblk = j4 >> 2;
            int oc = mblk*64 + row, ic = 2*(kc*8 + k2);
            const float* w = &w_in[(size_t)oc*64 + ic];
            x0 = w[0]; x1 = w[1];
        } else {
            int kc = cid - 840;
            int ic = 2*(kc*8 + k2);
            if (row < 64) {
                const float* w = &w_out[(size_t)row*128 + ic];
                x0 = w[0]; x1 = w[1];
            }
        }
        split2(x0, x1, hw[j], lw[j]);
    }
    g_afr[(size_t)cid*256 +       mg*32 + lane] = make_uint4(hw[0], hw[1], hw[2], hw[3]);
    g_afr[(size_t)cid*256 + 128 + mg*32 + lane] = make_uint4(lw[0], lw[1], lw[2], lw[3]);
}

// ---------------- unified bf16x3 GEMM (pipelined, 64m x 128n, frag-A) ----------------
__global__ void __launch_bounds__(256, 3)
gemm_bf3(int abase, int mystride, int nk, const void* __restrict__ Bin, int bsplit,
         const float* __restrict__ bias, const float* __restrict__ res,
         void* __restrict__ Out, int osplit, int Mtot)
{
    const int b  = blockIdx.z;
    const int m0 = blockIdx.y * 64, n0 = blockIdx.x * 128;
    const int cbase = abase + blockIdx.y * mystride;

    __shared__ __align__(16) uint4 As4[2][256];
    __shared__ uint32_t Bs[2][2][8][136];

    const int tid  = threadIdx.x;
    const int warp = tid >> 5, lane = tid & 31;
    const int wm = warp >> 2, wn = warp & 3;
    const int g = lane >> 2, t = lane & 3;

    const uint2* Bsp = (const uint2*)Bin + (size_t)b*(nk*8)*HW;
    const float* Bf  = (const float*)Bin + (size_t)b*(nk*16)*HW;

    float acc[2][4][4] = {};
    uint4 rA; uint2 rb[4];
    float f0[4], f1[4];

#define G_LOAD(c) do { \
        rA = g_afr[(size_t)(cbase + (c))*256 + tid]; \
        if (bsplit) { \
            _Pragma("unroll") \
            for (int j_ = 0; j_ < 4; j_++) { \
                int i_ = tid + j_*256; int tt_ = i_ >> 7; int n_ = i_ & 127; \
                rb[j_] = Bsp[(size_t)((c)*8 + tt_)*HW + n0 + n_]; \
            } \
        } else { \
            _Pragma("unroll") \
            for (int j_ = 0; j_ < 4; j_++) { \
                int i_ = tid + j_*256; int tt_ = i_ >> 7; int n_ = i_ & 127; \
                const float* xp_ = &Bf[(size_t)((c)*16 + 2*tt_)*HW + n0 + n_]; \
                f0[j_] = xp_[0]; f1[j_] = xp_[HW]; \
            } \
        } \
    } while(0)

#define G_STORE(s) do { \
        As4[s][tid] = rA; \
        _Pragma("unroll") \
        for (int j_ = 0; j_ < 4; j_++) { \
            int i_ = tid + j_*256; int tt_ = i_ >> 7; int n_ = i_ & 127; \
            if (bsplit) { \
                Bs[s][0][tt_][n_] = rb[j_].x; Bs[s][1][tt_][n_] = rb[j_].y; \
            } else { \
                uint32_t hi_, lo_; split2(f0[j_], f1[j_], hi_, lo_); \
                Bs[s][0][tt_][n_] = hi_; Bs[s][1][tt_][n_] = lo_; \
            } \
        } \
    } while(0)

    G_LOAD(0); G_STORE(0);
    __syncthreads();
    for (int c = 0; c < nk; c++) {
        const int cur = c & 1;
        if (c + 1 < nk) G_LOAD(c + 1);

        uint4 ah4[2], al4[2];
        #pragma unroll
        for (int mt = 0; mt < 2; mt++) {
            int mg = wm*2 + mt;
            ah4[mt] = As4[cur][      mg*32 + lane];
            al4[mt] = As4[cur][128 + mg*32 + lane];
        }
        #pragma unroll
        for (int nt = 0; nt < 4; nt++) {
            int col = wn*32 + nt*8 + g;
            uint32_t bh0 = Bs[cur][0][t][col], bh1 = Bs[cur][0][t+4][col];
            uint32_t bl0 = Bs[cur][1][t][col], bl1 = Bs[cur][1][t+4][col];
            #pragma unroll
            for (int mt = 0; mt < 2; mt++) {
                mma_bf16(acc[mt][nt], ah4[mt].x, ah4[mt].y, ah4[mt].z, ah4[mt].w, bh0, bh1);
                mma_bf16(acc[mt][nt], ah4[mt].x, ah4[mt].y, ah4[mt].z, ah4[mt].w, bl0, bl1);
                mma_bf16(acc[mt][nt], al4[mt].x, al4[mt].y, al4[mt].z, al4[mt].w, bh0, bh1);
            }
        }
        if (c + 1 < nk) G_STORE(cur ^ 1);
        __syncthreads();
    }
#undef G_LOAD
#undef G_STORE

    const float* Rb = res ? res + (size_t)b*Mtot*HW : nullptr;

    #pragma unroll
    for (int mt = 0; mt < 2; mt++) {
        const int row0 = m0 + wm*32 + mt*16 + g;
        const float b0v = bias ? bias[row0]     : 0.f;
        const float b1v = bias ? bias[row0 + 8] : 0.f;
        #pragma unroll
        for (int nt = 0; nt < 4; nt++) {
            int col = n0 + wn*32 + nt*8 + 2*t;
            float v00 = acc[mt][nt][0] + b0v, v01 = acc[mt][nt][1] + b0v;
            float v10 = acc[mt][nt][2] + b1v, v11 = acc[mt][nt][3] + b1v;
            if (Rb) {
                float2 r0 = *(const float2*)&Rb[(size_t)row0*HW + col];
                float2 r1 = *(const float2*)&Rb[(size_t)(row0+8)*HW + col];
                v00 += r0.x; v01 += r0.y; v10 += r1.x; v11 += r1.y;
            }
            if (!osplit) {
                float* Yb = (float*)Out + (size_t)b*Mtot*HW;
                *(float2*)&Yb[(size_t)row0*HW + col]     = make_float2(v00, v01);
                *(float2*)&Yb[(size_t)(row0+8)*HW + col] = make_float2(v10, v11);
            } else {
                float p00 = __shfl_xor_sync(0xffffffffu, v00, 4);
                float p01 = __shfl_xor_sync(0xffffffffu, v01, 4);
                float p10 = __shfl_xor_sync(0xffffffffu, v10, 4);
                float p11 = __shfl_xor_sync(0xffffffffu, v11, 4);
                if (!(g & 1)) {
                    uint2* Osp = (uint2*)Out + (size_t)b*(Mtot/2)*HW;
                    int c2 = row0 >> 1;
                    uint32_t h0,l0,h1,l1;
                    split2(v00, p00, h0, l0); split2(v01, p01, h1, l1);
                    *(uint4*)&Osp[(size_t)c2*HW + col] = make_uint4(h0,l0,h1,l1);
                    split2(v10, p10, h0, l0); split2(v11, p11, h1, l1);
                    *(uint4*)&Osp[(size_t)(c2+4)*HW + col] = make_uint4(h0,l0,h1,l1);
                }
            }
        }
    }
}

// ---------------- dilated 3x3 conv (bf16x3, pipelined, frag-A, 32m x 24n warps) ----
__global__ void __launch_bounds__(256, 3)
conv3x3_bf3(const uint2* __restrict__ Bsp, int abase, const float* __restrict__ bias,
            float* __restrict__ Y, int d)
{
    const int m0 = blockIdx.x * 64;
    const int y  = blockIdx.y;
    const int b  = blockIdx.z;
    const uint2* Xb = Bsp + (size_t)b*64*HW;

    __shared__ __align__(16) uint4 As4[2][256];
    __shared__ uint32_t Bs[2][2][8][104];
    __shared__ float sS[4][64], sQ[4][64];

    const int tid  = threadIdx.x;
    const int warp = tid >> 5, lane = tid & 31;
    const int wm = warp >> 2, wn = warp & 3;
    const int g = lane >> 2, t = lane & 3;

    int tapid[9], txs[9], roff[9], nv = 0;
    #pragma unroll
    for (int tap = 0; tap < 9; tap++) {
        int dy = tap/3 - 1, dx = tap%3 - 1;
        int yy = y + dy*d;
        if (yy >= 0 && yy < HH) {
            tapid[nv] = tap; txs[nv] = dx*d; roff[nv] = yy*WW; nv++;
        }
    }
    const int nchunks = nv * 8;

    float acc[2][3][4] = {};
    uint4 rA; uint2 rb[3];

#define C_LOAD(cc) do { \
        int tv_ = (cc) >> 3, kc_ = (cc) & 7; \
        int cid_ = abase + (tapid[tv_]*8 + kc_)*2 + blockIdx.x; \
        rA = g_afr[(size_t)cid_*256 + tid]; \
        const uint2* Xr_ = Xb + roff[tv_]; int sh_ = txs[tv_]; int icb_ = kc_*8; \
        _Pragma("unroll") \
        for (int j_ = 0; j_ < 3; j_++) { \
            int i_ = tid + j_*256; int tt_ = i_ / 96; int n_ = i_ - 96*tt_; \
            int xx_ = n_ + sh_; \
            rb[j_] = (xx_ >= 0 && xx_ < WW) ? Xr_[(size_t)(icb_ + tt_)*HW + xx_] \
                                            : make_uint2(0u, 0u); \
        } \
    } while(0)

#define C_STORE(s) do { \
        As4[s][tid] = rA; \
        _Pragma("unroll") \
        for (int j_ = 0; j_ < 3; j_++) { \
            int i_ = tid + j_*256; int tt_ = i_ / 96; int n_ = i_ - 96*tt_; \
            Bs[s][0][tt_][n_] = rb[j_].x; Bs[s][1][tt_][n_] = rb[j_].y; \
        } \
    } while(0)

    C_LOAD(0); C_STORE(0);
    __syncthreads();
    for (int cc = 0; cc < nchunks; cc++) {
        const int cur = cc & 1;
        if (cc + 1 < nchunks) C_LOAD(cc + 1);

        uint4 ah4[2], al4[2];
        #pragma unroll
        for (int mt = 0; mt < 2; mt++) {
            int mg = wm*2 + mt;
            ah4[mt] = As4[cur][      mg*32 + lane];
            al4[mt] = As4[cur][128 + mg*32 + lane];
        }
        #pragma unroll
        for (int nt = 0; nt < 3; nt++) {
            int col = wn*24 + nt*8 + g;
            uint32_t bh0 = Bs[cur][0][t][col], bh1 = Bs[cur][0][t+4][col];
            uint32_t bl0 = Bs[cur][1][t][col], bl1 = Bs[cur][1][t+4][col];
            #pragma unroll
            for (int mt = 0; mt < 2; mt++) {
                mma_bf16(acc[mt][nt], ah4[mt].x, ah4[mt].y, ah4[mt].z, ah4[mt].w, bh0, bh1);
                mma_bf16(acc[mt][nt], ah4[mt].x, ah4[mt].y, ah4[mt].z, ah4[mt].w, bl0, bl1);
                mma_bf16(acc[mt][nt], al4[mt].x, al4[mt].y, al4[mt].z, al4[mt].w, bh0, bh1);
            }
        }
        if (cc + 1 < nchunks) C_STORE(cur ^ 1);
        __syncthreads();
    }
#undef C_LOAD
#undef C_STORE

    float* Yb = Y + (size_t)b*DIM*HW + (size_t)y*WW;
    #pragma unroll
    for (int mt = 0; mt < 2; mt++) {
        const int row = wm*32 + mt*16 + g;          // in-tile 0..63
        const float b0v = bias[m0 + row], b1v = bias[m0 + row + 8];
        float s0 = 0.f, q0 = 0.f, s1 = 0.f, q1 = 0.f;
        #pragma unroll
        for (int nt = 0; nt < 3; nt++) {
            int col = wn*24 + nt*8 + 2*t;
            float v00 = acc[mt][nt][0] + b0v, v01 = acc[mt][nt][1] + b0v;
            float v10 = acc[mt][nt][2] + b1v, v11 = acc[mt][nt][3] + b1v;
            *(float2*)&Yb[(size_t)(m0 + row)*HW + col]     = make_float2(v00, v01);
            *(float2*)&Yb[(size_t)(m0 + row + 8)*HW + col] = make_float2(v10, v11);
            s0 += v00 + v01; q0 += v00*v00 + v01*v01;
            s1 += v10 + v11; q1 += v10*v10 + v11*v11;
        }
        #pragma unroll
        for (int o = 1; o <= 2; o <<= 1) {
            s0 += __shfl_xor_sync(0xffffffffu, s0, o);
            q0 += __shfl_xor_sync(0xffffffffu, q0, o);
            s1 += __shfl_xor_sync(0xffffffffu, s1, o);
            q1 += __shfl_xor_sync(0xffffffffu, q1, o);
        }
        if (t == 0) {
            sS[wn][row] = s0;     sQ[wn][row] = q0;
            sS[wn][row+8] = s1;   sQ[wn][row+8] = q1;
        }
    }
    __syncthreads();
    if (tid < 64) {
        int idx = b*HH + y;
        g_ps[(size_t)(m0+tid)*NIDX + idx] = sS[0][tid]+sS[1][tid]+sS[2][tid]+sS[3][tid];
        g_pq[(size_t)(m0+tid)*NIDX + idx] = sQ[0][tid]+sQ[1][tid]+sQ[2][tid]+sQ[3][tid];
    }
}

// ---------------- bn apply + relu (inline stats; 2304=9*256 so block has one c2) ----------------
__global__ void bn_apply_relu(const float* __restrict__ X, const float* __restrict__ gam,
                              const float* __restrict__ beta, float* __restrict__ Yf,
                              uint2* __restrict__ Ysp)
{
    const int b = blockIdx.y;
    int i = blockIdx.x*256 + threadIdx.x;
    int c2 = i / (HW/4);
    int p  = (i - c2*(HW/4)) * 4;
    int c0 = 2*c2, c1 = 2*c2 + 1;

    __shared__ float st[4];
    __shared__ float rs[4][8];
    {
        float s0=0.f, q0=0.f, s1=0.f, q1=0.f;
        int tt = threadIdx.x;
        if (tt < NIDX) {
            s0 = g_ps[(size_t)c0*NIDX + tt]; q0 = g_pq[(size_t)c0*NIDX + tt];
            s1 = g_ps[(size_t)c1*NIDX + tt]; q1 = g_pq[(size_t)c1*NIDX + tt];
        }
        #pragma unroll
        for (int o = 16; o > 0; o >>= 1) {
            s0 += __shfl_xor_sync(0xffffffffu, s0, o);
            q0 += __shfl_xor_sync(0xffffffffu, q0, o);
            s1 += __shfl_xor_sync(0xffffffffu, s1, o);
            q1 += __shfl_xor_sync(0xffffffffu, q1, o);
        }
        int w = threadIdx.x >> 5;
        if ((threadIdx.x & 31) == 0) {
            rs[0][w] = s0; rs[1][w] = q0; rs[2][w] = s1; rs[3][w] = q1;
        }
        __syncthreads();
        if (threadIdx.x == 0) {
            float S0=0,Q0=0,S1=0,Q1=0;
            #pragma unroll
            for (int k = 0; k < 8; k++) { S0+=rs[0][k]; Q0+=rs[1][k]; S1+=rs[2][k]; Q1+=rs[3][k]; }
            const float invN = 1.f / (BATCH*HW);
            float mm0 = S0*invN, mm1 = S1*invN;
            st[0] = mm0; st[1] = rsqrtf(Q0*invN - mm0*mm0 + 1e-5f);
            st[2] = mm1; st[3] = rsqrtf(Q1*invN - mm1*mm1 + 1e-5f);
        }
        __syncthreads();
    }
    float m0 = st[0], r0 = st[1], m1 = st[2], r1 = st[3];
    float ga0 = gam[c0], be0 = beta[c0], ga1 = gam[c1], be1 = beta[c1];

    const float* Xb = X + (size_t)b*DIM*HW;
    float* Yb = Yf + (size_t)b*DIM*HW;
    uint2* Sb = Ysp + (size_t)b*64*HW;

    float4 a = *(const float4*)&Xb[(size_t)c0*HW + p];
    float4 c = *(const float4*)&Xb[(size_t)c1*HW + p];
    float y0x = fmaxf((a.x-m0)*r0*ga0+be0, 0.f), y0y = fmaxf((a.y-m0)*r0*ga0+be0, 0.f);
    float y0z = fmaxf((a.z-m0)*r0*ga0+be0, 0.f), y0w = fmaxf((a.w-m0)*r0*ga0+be0, 0.f);
    float y1x = fmaxf((c.x-m1)*r1*ga1+be1, 0.f), y1y = fmaxf((c.y-m1)*r1*ga1+be1, 0.f);
    float y1z = fmaxf((c.z-m1)*r1*ga1+be1, 0.f), y1w = fmaxf((c.w-m1)*r1*ga1+be1, 0.f);

    *(float4*)&Yb[(size_t)c0*HW + p] = make_float4(y0x, y0y, y0z, y0w);
    *(float4*)&Yb[(size_t)c1*HW + p] = make_float4(y1x, y1y, y1z, y1w);

    uint32_t h0,l0,h1,l1,h2,l2,h3,l3;
    split2(y0x, y1x, h0, l0); split2(y0y, y1y, h1, l1);
    split2(y0z, y1z, h2, l2); split2(y0w, y1w, h3, l3);
    uint4* dst = (uint4*)&Sb[(size_t)c2*HW + p];
    dst[0] = make_uint4(h0, l0, h1, l1);
    dst[1] = make_uint4(h2, l2, h3, l3);
}

// ---------------- local channel self-attention (split epilogue) ----------------
__global__ void attn_core(const float* __restrict__ QKV, uint2* __restrict__ OUT)
{
    const int b = blockIdx.z, h = blockIdx.y;
    const int p0 = blockIdx.x * 32;
    const int y  = p0 / WW, x0 = p0 % WW;
    const float* Qb = QKV + ((size_t)b*3*DIM + h*CH)*HW;
    const float* Kb = Qb + (size_t)DIM*HW;
    const float* Vb = Qb + (size_t)2*DIM*HW;

    __shared__ float qs[CH][3][34];
    __shared__ float ks[CH][3][34];
    __shared__ float vs[CH][3][34];
    __shared__ float sato[CH][33];

    const int tid = threadIdx.y*32 + threadIdx.x;
    for (int i = tid; i < CH*3*34; i += 512) {
        int xi = i % 34; int rr = i / 34; int yi = rr % 3; int c = rr / 3;
        int yy = y + yi - 1, xx = x0 + xi - 1;
        bool ok = (yy >= 0 && yy < HH && xx >= 0 && xx < WW);
        int o = c*HW + yy*WW + xx;
        qs[c][yi][xi] = ok ? Qb[o] : 0.f;
        ks[c][yi][xi] = ok ? Kb[o] : 0.f;
        vs[c][yi][xi] = ok ? Vb[o] : 0.f;
    }
    __syncthreads();

    const int nn = threadIdx.y, lx = threadIdx.x;
    float qr[9];
    #pragma unroll
    for (int t = 0; t < 9; t++) qr[t] = qs[nn][t/3][lx + t%3] * 0.25f;

    float dots[CH], vsum[CH];
    #pragma unroll
    for (int m = 0; m < CH; m++) {
        float dv = 0.f, sv = 0.f;
        #pragma unroll
        for (int t = 0; t < 9; t++) {
            dv += qr[t] * ks[m][t/3][lx + t%3];
            sv += vs[m][t/3][lx + t%3];
        }
        dots[m] = dv; vsum[m] = sv;
    }
    float mx = dots[0];
    #pragma unroll
    for (int m = 1; m < CH; m++) mx = fmaxf(mx, dots[m]);
    float s = 0.f;
    #pragma unroll
    for (int m = 0; m < CH; m++) { dots[m] = __expf(dots[m]-mx); s += dots[m]; }
    float o = 0.f;
    #pragma unroll
    for (int m = 0; m < CH; m++) o += dots[m]*vsum[m];
    sato[nn][lx] = o / s;
    __syncthreads();

    if (nn < 8) {
        float v0 = sato[2*nn][lx], v1 = sato[2*nn+1][lx];
        uint32_t hi, lo; split2(v0, v1, hi, lo);
        OUT[(size_t)b*64*HW + (size_t)(h*8 + nn)*HW + p0 + lx] = make_uint2(hi, lo);
    }
}

// ---------------- host orchestration ----------------
extern "C" void kernel_launch(void* const* d_in, const int* in_sizes, int n_in,
                              void* d_out, int out_size)
{
    const float* x      = (const float*)d_in[0];
    const float* b_in   = (const float*)d_in[2];
    const float* conv_w = (const float*)d_in[3];
    const float* conv_b = (const float*)d_in[4];
    const float* bn_g   = (const float*)d_in[5];
    const float* bn_b   = (const float*)d_in[6];
    const float* qkv_w  = (const float*)d_in[7];
    const float* fc_w   = (const float*)d_in[8];
    const float* fc_b   = (const float*)d_in[9];
    const float* w_in   = (const float*)d_in[1];
    const float* w_out  = (const float*)d_in[10];
    const float* b_out  = (const float*)d_in[11];
    float* out = (float*)d_out;

    float *p_t, *p_bn, *p_qkv;
    uint2 *p_hsp, *p_qsp, *p_asp;
    cudaGetSymbolAddress((void**)&p_t,   g_t);
    cudaGetSymbolAddress((void**)&p_bn,  g_bn);
    cudaGetSymbolAddress((void**)&p_qkv, g_qkv);
    cudaGetSymbolAddress((void**)&p_hsp, g_hsp);
    cudaGetSymbolAddress((void**)&p_qsp, g_qsp);
    cudaGetSymbolAddress((void**)&p_asp, g_asp);

    prep_afr<<<(NCID*128 + 255)/256, 256>>>(conv_w, qkv_w, fc_w, w_in, w_out);

    // input projection 64 -> 128: abase 832, mystride 4, nk 4, fp32 B, split out
    {
        dim3 g(HW/128, DIM/64, BATCH);
        gemm_bf3<<<g, 256>>>(832, 4, 4, x, 0, b_in, nullptr, p_hsp, 1, DIM);
    }

    for (int i = 0; i < DEPTH; i++) {
        const int d = 1 << i;
        {   // dilated conv: abase = i*144
            dim3 g(2, HH, BATCH);
            conv3x3_bf3<<<g, 256>>>(p_hsp, i*144, conv_b + i*DIM, p_t, d);
        }
        {   // bn + relu -> fp32 residual + split qkv input
            dim3 g((64*HW/4)/256, BATCH);
            bn_apply_relu<<<g, 256>>>(p_t, bn_g + i*DIM, bn_b + i*DIM, p_bn, p_qsp);
        }
        {   // qkv: abase = 576 + i*48, 6 m-blocks
            dim3 g(HW/128, (3*DIM)/64, BATCH);
            gemm_bf3<<<g, 256>>>(576 + i*48, 8, 8, p_qsp, 1, nullptr, nullptr,
                                 p_qkv, 0, 3*DIM);
        }
        {   // attention -> split att
            dim3 g(HW/32, HEADS, BATCH);
            dim3 blk(32, CH);
            attn_core<<<g, blk>>>(p_qkv, p_asp);
        }
        {   // fc + bias + residual -> split h; abase = 768 + i*16
            dim3 g(HW/128, DIM/64, BATCH);
            gemm_bf3<<<g, 256>>>(768 + i*16, 8, 8, p_asp, 1, fc_b + i*DIM, p_bn,
                                 p_hsp, 1, DIM);
        }
    }

    // output projection 128 -> 64: abase 840
    {
        dim3 g(HW/128, COUT/64, BATCH);
        gemm_bf3<<<g, 256>>>(840, 0, 8, p_hsp, 1, b_out, nullptr, out, 0, COUT);
    }
}

// round 9
// speedup vs baseline: 1.4266x; 1.4266x over previous
#include <cuda_runtime.h>
#include <cuda_bf16.h>
#include <cstdint>
#include <cstddef>

#define BATCH 2
#define DIM 128
#define CIN 64
#define COUT 64
#define HH 96
#define WW 96
#define HW (HH*WW)           // 9216
#define HEADS 8
#define CH 16
#define DEPTH 4
#define NIDX (BATCH*HH)      // 192 (b,y) slots for bn partials

// ---------------- scratch (device globals) ----------------
__device__ __align__(16) float g_t  [BATCH*DIM*HW];   // conv out (fp32, pre-BN)
__device__ __align__(16) float g_bn [BATCH*DIM*HW];   // bn+relu out (fp32 residual)
__device__ __align__(16) float g_qkv[BATCH*3*DIM*HW];
__device__ __align__(16) uint2 g_hsp[BATCH*64*HW];    // split h   (conv / out-proj B)
__device__ __align__(16) uint2 g_qsp[BATCH*64*HW];    // split bn  (qkv B)
__device__ __align__(16) uint2 g_asp[BATCH*64*HW];    // split att (fc B)
__device__ float g_ps[DIM*NIDX];
__device__ float g_pq[DIM*NIDX];
// packed split weights: uint2 {hi,lo}, layout [K/2][M]
__device__ uint2 g_cw[DEPTH*9*64*DIM];   // [d][tap][ic2][oc]
__device__ uint2 g_qw[DEPTH*64*3*DIM];
__device__ uint2 g_fw[DEPTH*64*DIM];
__device__ uint2 g_wi[32*DIM];
__device__ uint2 g_wo[64*COUT];

__device__ __forceinline__ void split2(float x0, float x1, uint32_t& hi, uint32_t& lo)
{
    __nv_bfloat16 h0 = __float2bfloat16(x0);
    __nv_bfloat16 h1 = __float2bfloat16(x1);
    float l0f = x0 - __bfloat162float(h0);
    float l1f = x1 - __bfloat162float(h1);
    __nv_bfloat162 hh = __halves2bfloat162(h0, h1);
    __nv_bfloat162 ll = __halves2bfloat162(__float2bfloat16(l0f), __float2bfloat16(l1f));
    hi = *reinterpret_cast<uint32_t*>(&hh);
    lo = *reinterpret_cast<uint32_t*>(&ll);
}

__device__ __forceinline__ void mma_bf16(float c[4],
    uint32_t a0, uint32_t a1, uint32_t a2, uint32_t a3, uint32_t b0, uint32_t b1)
{
    asm volatile(
        "mma.sync.aligned.m16n8k16.row.col.f32.bf16.bf16.f32 "
        "{%0,%1,%2,%3}, {%4,%5,%6,%7}, {%8,%9}, {%0,%1,%2,%3};"
        : "+f"(c[0]), "+f"(c[1]), "+f"(c[2]), "+f"(c[3])
        : "r"(a0), "r"(a1), "r"(a2), "r"(a3), "r"(b0), "r"(b1));
}

// ---------------- unified weight prep (single launch) ----------------
#define NC (DEPTH*9*64*DIM)
#define NQ (DEPTH*64*3*DIM)
#define NF (DEPTH*64*DIM)
#define NI (32*DIM)
#define NO (64*COUT)
__global__ void prep_all(const float* __restrict__ conv_w, const float* __restrict__ qkv_w,
                         const float* __restrict__ fc_w, const float* __restrict__ w_in,
                         const float* __restrict__ w_out)
{
    int i = blockIdx.x*256 + threadIdx.x;
    float x0, x1; uint2* dst;
    if (i < NC) {
        int oc = i & 127; int r = i >> 7; int ic2 = r & 63; r >>= 6;
        int tap = r % 9, d = r / 9;
        size_t base = ((size_t)(d*DIM + oc)*DIM + 2*ic2)*9 + tap;
        x0 = conv_w[base]; x1 = conv_w[base + 9]; dst = &g_cw[i];
    } else if (i < NC+NQ) {
        int j = i - NC; int d = j / (64*384); int l = j % (64*384);
        int k2 = l / 384, m = l % 384;
        x0 = qkv_w[((size_t)d*384 + m)*DIM + 2*k2];
        x1 = qkv_w[((size_t)d*384 + m)*DIM + 2*k2 + 1];
        dst = &g_qw[j];
    } else if (i < NC+NQ+NF) {
        int j = i - NC - NQ; int d = j / (64*DIM); int l = j % (64*DIM);
        int k2 = l / DIM, m = l % DIM;
        x0 = fc_w[((size_t)d*DIM + m)*DIM + 2*k2];
        x1 = fc_w[((size_t)d*DIM + m)*DIM + 2*k2 + 1];
        dst = &g_fw[j];
    } else if (i < NC+NQ+NF+NI) {
        int j = i - NC - NQ - NF; int k2 = j / DIM, m = j % DIM;
        x0 = w_in[(size_t)m*CIN + 2*k2]; x1 = w_in[(size_t)m*CIN + 2*k2 + 1];
        dst = &g_wi[j];
    } else if (i < NC+NQ+NF+NI+NO) {
        int j = i - NC - NQ - NF - NI; int k2 = j / COUT, m = j % COUT;
        x0 = w_out[(size_t)m*DIM + 2*k2]; x1 = w_out[(size_t)m*DIM + 2*k2 + 1];
        dst = &g_wo[j];
    } else return;
    uint32_t hi, lo; split2(x0, x1, hi, lo);
    *dst = make_uint2(hi, lo);
}

// ---------------- unified bf16x3 GEMM (2-stage pipelined, 64m x 128n block) ----------------
__global__ void gemm_bf3(const uint2* __restrict__ W, const void* __restrict__ Bin, int bsplit,
                         const float* __restrict__ bias, const float* __restrict__ res,
                         void* __restrict__ Out, int osplit, int Mtot, int K)
{
    const int b  = blockIdx.z;
    const int m0 = blockIdx.y * 64, n0 = blockIdx.x * 128;

    __shared__ uint32_t As[2][2][8][72];
    __shared__ uint32_t Bs[2][2][8][136];

    const int tid  = threadIdx.x;
    const int warp = tid >> 5, lane = tid & 31;
    const int wm = warp >> 2, wn = warp & 3;
    const int g = lane >> 2, t = lane & 3;
    const int tt0 = tid >> 6, mcol = tid & 63;

    const uint2* Bsp = (const uint2*)Bin + (size_t)b*(K/2)*HW;
    const float* Bf  = (const float*)Bin + (size_t)b*K*HW;

    const int nk = K/16;
    float acc[2][4][4] = {};

    uint2 ra0, ra1, rb[4];
    float f0[4], f1[4];

#define G_LOAD(c) do { \
        ra0 = W[(size_t)((c)*8 + tt0)*Mtot + m0 + mcol]; \
        ra1 = W[(size_t)((c)*8 + tt0 + 4)*Mtot + m0 + mcol]; \
        if (bsplit) { \
            _Pragma("unroll") \
            for (int j_ = 0; j_ < 4; j_++) { \
                int i_ = tid + j_*256; int tt_ = i_ >> 7; int n_ = i_ & 127; \
                rb[j_] = Bsp[(size_t)((c)*8 + tt_)*HW + n0 + n_]; \
            } \
        } else { \
            _Pragma("unroll") \
            for (int j_ = 0; j_ < 4; j_++) { \
                int i_ = tid + j_*256; int tt_ = i_ >> 7; int n_ = i_ & 127; \
                const float* xp_ = &Bf[(size_t)((c)*16 + 2*tt_)*HW + n0 + n_]; \
                f0[j_] = xp_[0]; f1[j_] = xp_[HW]; \
            } \
        } \
    } while(0)

#define G_STORE(s) do { \
        As[s][0][tt0][mcol] = ra0.x;   As[s][1][tt0][mcol] = ra0.y; \
        As[s][0][tt0+4][mcol] = ra1.x; As[s][1][tt0+4][mcol] = ra1.y; \
        _Pragma("unroll") \
        for (int j_ = 0; j_ < 4; j_++) { \
            int i_ = tid + j_*256; int tt_ = i_ >> 7; int n_ = i_ & 127; \
            if (bsplit) { \
                Bs[s][0][tt_][n_] = rb[j_].x; Bs[s][1][tt_][n_] = rb[j_].y; \
            } else { \
                uint32_t hi_, lo_; split2(f0[j_], f1[j_], hi_, lo_); \
                Bs[s][0][tt_][n_] = hi_; Bs[s][1][tt_][n_] = lo_; \
            } \
        } \
    } while(0)

    G_LOAD(0); G_STORE(0);
    __syncthreads();
    for (int c = 0; c < nk; c++) {
        const int cur = c & 1;
        if (c + 1 < nk) G_LOAD(c + 1);

        uint32_t ah[2][4], al[2][4];
        #pragma unroll
        for (int mt = 0; mt < 2; mt++) {
            int mrow = wm*32 + mt*16 + g;
            ah[mt][0] = As[cur][0][t  ][mrow]; ah[mt][1] = As[cur][0][t  ][mrow+8];
            ah[mt][2] = As[cur][0][t+4][mrow]; ah[mt][3] = As[cur][0][t+4][mrow+8];
            al[mt][0] = As[cur][1][t  ][mrow]; al[mt][1] = As[cur][1][t  ][mrow+8];
            al[mt][2] = As[cur][1][t+4][mrow]; al[mt][3] = As[cur][1][t+4][mrow+8];
        }
        #pragma unroll
        for (int nt = 0; nt < 4; nt++) {
            int col = wn*32 + nt*8 + g;
            uint32_t bh0 = Bs[cur][0][t][col], bh1 = Bs[cur][0][t+4][col];
            uint32_t bl0 = Bs[cur][1][t][col], bl1 = Bs[cur][1][t+4][col];
            #pragma unroll
            for (int mt = 0; mt < 2; mt++) {
                mma_bf16(acc[mt][nt], ah[mt][0], ah[mt][1], ah[mt][2], ah[mt][3], bh0, bh1);
                mma_bf16(acc[mt][nt], ah[mt][0], ah[mt][1], ah[mt][2], ah[mt][3], bl0, bl1);
                mma_bf16(acc[mt][nt], al[mt][0], al[mt][1], al[mt][2], al[mt][3], bh0, bh1);
            }
        }
        if (c + 1 < nk) G_STORE(cur ^ 1);
        __syncthreads();
    }
#undef G_LOAD
#undef G_STORE

    const float* Rb = res ? res + (size_t)b*Mtot*HW : nullptr;

    #pragma unroll
    for (int mt = 0; mt < 2; mt++) {
        const int row0 = m0 + wm*32 + mt*16 + g;
        const float b0v = bias ? bias[row0]     : 0.f;
        const float b1v = bias ? bias[row0 + 8] : 0.f;
        #pragma unroll
        for (int nt = 0; nt < 4; nt++) {
            int col = n0 + wn*32 + nt*8 + 2*t;
            float v00 = acc[mt][nt][0] + b0v, v01 = acc[mt][nt][1] + b0v;
            float v10 = acc[mt][nt][2] + b1v, v11 = acc[mt][nt][3] + b1v;
            if (Rb) {
                float2 r0 = *(const float2*)&Rb[(size_t)row0*HW + col];
                float2 r1 = *(const float2*)&Rb[(size_t)(row0+8)*HW + col];
                v00 += r0.x; v01 += r0.y; v10 += r1.x; v11 += r1.y;
            }
            if (!osplit) {
                float* Yb = (float*)Out + (size_t)b*Mtot*HW;
                *(float2*)&Yb[(size_t)row0*HW + col]     = make_float2(v00, v01);
                *(float2*)&Yb[(size_t)(row0+8)*HW + col] = make_float2(v10, v11);
            } else {
                float p00 = __shfl_xor_sync(0xffffffffu, v00, 4);
                float p01 = __shfl_xor_sync(0xffffffffu, v01, 4);
                float p10 = __shfl_xor_sync(0xffffffffu, v10, 4);
                float p11 = __shfl_xor_sync(0xffffffffu, v11, 4);
                if (!(g & 1)) {
                    uint2* Osp = (uint2*)Out + (size_t)b*(Mtot/2)*HW;
                    int c2 = row0 >> 1;
                    uint32_t h0,l0,h1,l1;
                    split2(v00, p00, h0, l0); split2(v01, p01, h1, l1);
                    *(uint4*)&Osp[(size_t)c2*HW + col] = make_uint4(h0,l0,h1,l1);
                    split2(v10, p10, h0, l0); split2(v11, p11, h1, l1);
                    *(uint4*)&Osp[(size_t)(c2+4)*HW + col] = make_uint4(h0,l0,h1,l1);
                }
            }
        }
    }
}

// ---------------- dilated 3x3 conv (bf16x3, pipelined, 2 rows per block: 64m x 192n) ----
// 8 warps as 4m x 2n; warp wn owns row y0+wn entirely (96 px x 16 ch).
__global__ void conv3x3_bf3(const uint2* __restrict__ Bsp, const uint2* __restrict__ CW,
                            const float* __restrict__ bias, float* __restrict__ Y, int d)
{
    const int m0 = blockIdx.x * 64;
    const int y0 = blockIdx.y * 2;
    const int b  = blockIdx.z;
    const uint2* Xb = Bsp + (size_t)b*64*HW;

    __shared__ uint32_t As[2][2][8][72];
    __shared__ uint32_t Bs[2][2][8][200];
    __shared__ float sS[2][64], sQ[2][64];

    const int tid  = threadIdx.x;
    const int warp = tid >> 5, lane = tid & 31;
    const int wm = warp >> 1, wn = warp & 1;
    const int g = lane >> 2, t = lane & 3;
    const int tt0 = tid >> 6, mcol = tid & 63;

    // tap list: keep tap if either row is valid
    int tidx[9], txs[9], tdy[9], nv = 0;
    #pragma unroll
    for (int tap = 0; tap < 9; tap++) {
        int dy = tap/3 - 1, dx = tap%3 - 1;
        int r0 = y0 + dy*d;
        if ((r0 >= 0 && r0 < HH) || (r0+1 >= 0 && r0+1 < HH)) {
            tidx[nv] = tap; txs[nv] = dx*d; tdy[nv] = dy*d; nv++;
        }
    }
    const int nchunks = nv * 8;

    float acc[12][4] = {};
    uint2 ra0, ra1, rb[6];

#define C_LOAD(cc) do { \
        int tv_ = (cc) >> 3, kc_ = (cc) & 7; int icb_ = kc_*8; \
        const uint2* Wt_ = CW + (size_t)tidx[tv_]*64*DIM; \
        ra0 = Wt_[(size_t)(icb_ + tt0)*DIM + m0 + mcol]; \
        ra1 = Wt_[(size_t)(icb_ + tt0 + 4)*DIM + m0 + mcol]; \
        int sh_ = txs[tv_], dy_ = tdy[tv_]; \
        _Pragma("unroll") \
        for (int j_ = 0; j_ < 6; j_++) { \
            int i_ = tid + j_*256; int tt_ = i_ / 192; int n_ = i_ - 192*tt_; \
            int h_ = n_ / 96; int px_ = n_ - 96*h_; \
            int row_ = y0 + h_ + dy_; int xx_ = px_ + sh_; \
            rb[j_] = (row_ >= 0 && row_ < HH && xx_ >= 0 && xx_ < WW) \
                   ? Xb[(size_t)(icb_ + tt_)*HW + row_*WW + xx_] : make_uint2(0u, 0u); \
        } \
    } while(0)

#define C_STORE(s) do { \
        As[s][0][tt0][mcol] = ra0.x;   As[s][1][tt0][mcol] = ra0.y; \
        As[s][0][tt0+4][mcol] = ra1.x; As[s][1][tt0+4][mcol] = ra1.y; \
        _Pragma("unroll") \
        for (int j_ = 0; j_ < 6; j_++) { \
            int i_ = tid + j_*256; int tt_ = i_ / 192; int n_ = i_ - 192*tt_; \
            Bs[s][0][tt_][n_] = rb[j_].x; Bs[s][1][tt_][n_] = rb[j_].y; \
        } \
    } while(0)

    C_LOAD(0); C_STORE(0);
    __syncthreads();
    for (int cc = 0; cc < nchunks; cc++) {
        const int cur = cc & 1;
        if (cc + 1 < nchunks) C_LOAD(cc + 1);

        const int mrow = wm*16 + g;
        uint32_t ah0 = As[cur][0][t  ][mrow], ah1 = As[cur][0][t  ][mrow+8];
        uint32_t ah2 = As[cur][0][t+4][mrow], ah3 = As[cur][0][t+4][mrow+8];
        uint32_t al0 = As[cur][1][t  ][mrow], al1 = As[cur][1][t  ][mrow+8];
        uint32_t al2 = As[cur][1][t+4][mrow], al3 = As[cur][1][t+4][mrow+8];
        #pragma unroll
        for (int nt = 0; nt < 12; nt++) {
            int col = wn*96 + nt*8 + g;
            uint32_t bh0 = Bs[cur][0][t][col], bh1 = Bs[cur][0][t+4][col];
            uint32_t bl0 = Bs[cur][1][t][col], bl1 = Bs[cur][1][t+4][col];
            mma_bf16(acc[nt], ah0, ah1, ah2, ah3, bh0, bh1);
            mma_bf16(acc[nt], ah0, ah1, ah2, ah3, bl0, bl1);
            mma_bf16(acc[nt], al0, al1, al2, al3, bh0, bh1);
        }
        if (cc + 1 < nchunks) C_STORE(cur ^ 1);
        __syncthreads();
    }
#undef C_LOAD
#undef C_STORE

    // epilogue: warp wn owns row y0+wn
    float* Yb = Y + (size_t)b*DIM*HW + (size_t)(y0 + wn)*WW;
    const int row0 = m0 + wm*16 + g;
    const float b0v = bias[row0], b1v = bias[row0 + 8];
    float s0 = 0.f, q0 = 0.f, s1 = 0.f, q1 = 0.f;
    #pragma unroll
    for (int nt = 0; nt < 12; nt++) {
        int col = nt*8 + 2*t;
        float v00 = acc[nt][0] + b0v, v01 = acc[nt][1] + b0v;
        float v10 = acc[nt][2] + b1v, v11 = acc[nt][3] + b1v;
        *(float2*)&Yb[(size_t)row0*HW + col]     = make_float2(v00, v01);
        *(float2*)&Yb[(size_t)(row0+8)*HW + col] = make_float2(v10, v11);
        s0 += v00 + v01; q0 += v00*v00 + v01*v01;
        s1 += v10 + v11; q1 += v10*v10 + v11*v11;
    }
    #pragma unroll
    for (int o = 1; o <= 2; o <<= 1) {
        s0 += __shfl_xor_sync(0xffffffffu, s0, o);
        q0 += __shfl_xor_sync(0xffffffffu, q0, o);
        s1 += __shfl_xor_sync(0xffffffffu, s1, o);
        q1 += __shfl_xor_sync(0xffffffffu, q1, o);
    }
    if (t == 0) {
        int lr = wm*16 + g;
        sS[wn][lr] = s0;   sQ[wn][lr] = q0;
        sS[wn][lr+8] = s1; sQ[wn][lr+8] = q1;
    }
    __syncthreads();
    if (tid < 128) {
        int ch = tid & 63, r = tid >> 6;
        g_ps[(size_t)(m0+ch)*NIDX + b*HH + y0 + r] = sS[r][ch];
        g_pq[(size_t)(m0+ch)*NIDX + b*HH + y0 + r] = sQ[r][ch];
    }
}

// ---------------- bn apply + relu (inline stats; 2304=9*256 so block has one c2) ----------------
__global__ void bn_apply_relu(const float* __restrict__ X, const float* __restrict__ gam,
                              const float* __restrict__ beta, float* __restrict__ Yf,
                              uint2* __restrict__ Ysp)
{
    const int b = blockIdx.y;
    int i = blockIdx.x*256 + threadIdx.x;
    int c2 = i / (HW/4);
    int p  = (i - c2*(HW/4)) * 4;
    int c0 = 2*c2, c1 = 2*c2 + 1;

    __shared__ float st[4];
    __shared__ float rs[4][8];
    {
        float s0=0.f, q0=0.f, s1=0.f, q1=0.f;
        int tt = threadIdx.x;
        if (tt < NIDX) {
            s0 = g_ps[(size_t)c0*NIDX + tt]; q0 = g_pq[(size_t)c0*NIDX + tt];
            s1 = g_ps[(size_t)c1*NIDX + tt]; q1 = g_pq[(size_t)c1*NIDX + tt];
        }
        #pragma unroll
        for (int o = 16; o > 0; o >>= 1) {
            s0 += __shfl_xor_sync(0xffffffffu, s0, o);
            q0 += __shfl_xor_sync(0xffffffffu, q0, o);
            s1 += __shfl_xor_sync(0xffffffffu, s1, o);
            q1 += __shfl_xor_sync(0xffffffffu, q1, o);
        }
        int w = threadIdx.x >> 5;
        if ((threadIdx.x & 31) == 0) {
            rs[0][w] = s0; rs[1][w] = q0; rs[2][w] = s1; rs[3][w] = q1;
        }
        __syncthreads();
        if (threadIdx.x == 0) {
            float S0=0,Q0=0,S1=0,Q1=0;
            #pragma unroll
            for (int k = 0; k < 8; k++) { S0+=rs[0][k]; Q0+=rs[1][k]; S1+=rs[2][k]; Q1+=rs[3][k]; }
            const float invN = 1.f / (BATCH*HW);
            float mm0 = S0*invN, mm1 = S1*invN;
            st[0] = mm0; st[1] = rsqrtf(Q0*invN - mm0*mm0 + 1e-5f);
            st[2] = mm1; st[3] = rsqrtf(Q1*invN - mm1*mm1 + 1e-5f);
        }
        __syncthreads();
    }
    float m0 = st[0], r0 = st[1], m1 = st[2], r1 = st[3];
    float ga0 = gam[c0], be0 = beta[c0], ga1 = gam[c1], be1 = beta[c1];

    const float* Xb = X + (size_t)b*DIM*HW;
    float* Yb = Yf + (size_t)b*DIM*HW;
    uint2* Sb = Ysp + (size_t)b*64*HW;

    float4 a = *(const float4*)&Xb[(size_t)c0*HW + p];
    float4 c = *(const float4*)&Xb[(size_t)c1*HW + p];
    float y0x = fmaxf((a.x-m0)*r0*ga0+be0, 0.f), y0y = fmaxf((a.y-m0)*r0*ga0+be0, 0.f);
    float y0z = fmaxf((a.z-m0)*r0*ga0+be0, 0.f), y0w = fmaxf((a.w-m0)*r0*ga0+be0, 0.f);
    float y1x = fmaxf((c.x-m1)*r1*ga1+be1, 0.f), y1y = fmaxf((c.y-m1)*r1*ga1+be1, 0.f);
    float y1z = fmaxf((c.z-m1)*r1*ga1+be1, 0.f), y1w = fmaxf((c.w-m1)*r1*ga1+be1, 0.f);

    *(float4*)&Yb[(size_t)c0*HW + p] = make_float4(y0x, y0y, y0z, y0w);
    *(float4*)&Yb[(size_t)c1*HW + p] = make_float4(y1x, y1y, y1z, y1w);

    uint32_t h0,l0,h1,l1,h2,l2,h3,l3;
    split2(y0x, y1x, h0, l0); split2(y0y, y1y, h1, l1);
    split2(y0z, y1z, h2, l2); split2(y0w, y1w, h3, l3);
    uint4* dst = (uint4*)&Sb[(size_t)c2*HW + p];
    dst[0] = make_uint4(h0, l0, h1, l1);
    dst[1] = make_uint4(h2, l2, h3, l3);
}

// ---------------- local channel self-attention (split epilogue) ----------------
__global__ void attn_core(const float* __restrict__ QKV, uint2* __restrict__ OUT)
{
    const int b = blockIdx.z, h = blockIdx.y;
    const int p0 = blockIdx.x * 32;
    const int y  = p0 / WW, x0 = p0 % WW;
    const float* Qb = QKV + ((size_t)b*3*DIM + h*CH)*HW;
    const float* Kb = Qb + (size_t)DIM*HW;
    const float* Vb = Qb + (size_t)2*DIM*HW;

    __shared__ float qs[CH][3][34];
    __shared__ float ks[CH][3][34];
    __shared__ float vs[CH][3][34];
    __shared__ float sato[CH][33];

    const int tid = threadIdx.y*32 + threadIdx.x;
    for (int i = tid; i < CH*3*34; i += 512) {
        int xi = i % 34; int rr = i / 34; int yi = rr % 3; int c = rr / 3;
        int yy = y + yi - 1, xx = x0 + xi - 1;
        bool ok = (yy >= 0 && yy < HH && xx >= 0 && xx < WW);
        int o = c*HW + yy*WW + xx;
        qs[c][yi][xi] = ok ? Qb[o] : 0.f;
        ks[c][yi][xi] = ok ? Kb[o] : 0.f;
        vs[c][yi][xi] = ok ? Vb[o] : 0.f;
    }
    __syncthreads();

    const int nn = threadIdx.y, lx = threadIdx.x;
    float qr[9];
    #pragma unroll
    for (int t = 0; t < 9; t++) qr[t] = qs[nn][t/3][lx + t%3] * 0.25f;

    float dots[CH], vsum[CH];
    #pragma unroll
    for (int m = 0; m < CH; m++) {
        float dv = 0.f, sv = 0.f;
        #pragma unroll
        for (int t = 0; t < 9; t++) {
            dv += qr[t] * ks[m][t/3][lx + t%3];
            sv += vs[m][t/3][lx + t%3];
        }
        dots[m] = dv; vsum[m] = sv;
    }
    float mx = dots[0];
    #pragma unroll
    for (int m = 1; m < CH; m++) mx = fmaxf(mx, dots[m]);
    float s = 0.f;
    #pragma unroll
    for (int m = 0; m < CH; m++) { dots[m] = __expf(dots[m]-mx); s += dots[m]; }
    float o = 0.f;
    #pragma unroll
    for (int m = 0; m < CH; m++) o += dots[m]*vsum[m];
    sato[nn][lx] = o / s;
    __syncthreads();

    if (nn < 8) {
        float v0 = sato[2*nn][lx], v1 = sato[2*nn+1][lx];
        uint32_t hi, lo; split2(v0, v1, hi, lo);
        OUT[(size_t)b*64*HW + (size_t)(h*8 + nn)*HW + p0 + lx] = make_uint2(hi, lo);
    }
}

// ---------------- host orchestration ----------------
extern "C" void kernel_launch(void* const* d_in, const int* in_sizes, int n_in,
                              void* d_out, int out_size)
{
    const float* x      = (const float*)d_in[0];
    const float* w_in   = (const float*)d_in[1];
    const float* b_in   = (const float*)d_in[2];
    const float* conv_w = (const float*)d_in[3];
    const float* conv_b = (const float*)d_in[4];
    const float* bn_g   = (const float*)d_in[5];
    const float* bn_b   = (const float*)d_in[6];
    const float* qkv_w  = (const float*)d_in[7];
    const float* fc_w   = (const float*)d_in[8];
    const float* fc_b   = (const float*)d_in[9];
    const float* w_out  = (const float*)d_in[10];
    const float* b_out  = (const float*)d_in[11];
    float* out = (float*)d_out;

    float *p_t, *p_bn, *p_qkv;
    uint2 *p_hsp, *p_qsp, *p_asp, *p_cw, *p_qw, *p_fw, *p_wi, *p_wo;
    cudaGetSymbolAddress((void**)&p_t,   g_t);
    cudaGetSymbolAddress((void**)&p_bn,  g_bn);
    cudaGetSymbolAddress((void**)&p_qkv, g_qkv);
    cudaGetSymbolAddress((void**)&p_hsp, g_hsp);
    cudaGetSymbolAddress((void**)&p_qsp, g_qsp);
    cudaGetSymbolAddress((void**)&p_asp, g_asp);
    cudaGetSymbolAddress((void**)&p_cw,  g_cw);
    cudaGetSymbolAddress((void**)&p_qw,  g_qw);
    cudaGetSymbolAddress((void**)&p_fw,  g_fw);
    cudaGetSymbolAddress((void**)&p_wi,  g_wi);
    cudaGetSymbolAddress((void**)&p_wo,  g_wo);

    prep_all<<<(NC+NQ+NF+NI+NO + 255)/256, 256>>>(conv_w, qkv_w, fc_w, w_in, w_out);

    // input projection 64 -> 128, split output into g_hsp
    {
        dim3 g(HW/128, DIM/64, BATCH);
        gemm_bf3<<<g, 256>>>(p_wi, x, 0, b_in, nullptr, p_hsp, 1, DIM, CIN);
    }

    for (int i = 0; i < DEPTH; i++) {
        const int d = 1 << i;
        {   // dilated conv: 2 rows per block
            dim3 g(2, HH/2, BATCH);
            conv3x3_bf3<<<g, 256>>>(p_hsp, p_cw + (size_t)i*9*64*DIM,
                                    conv_b + i*DIM, p_t, d);
        }
        {
            dim3 g((64*HW/4)/256, BATCH);
            bn_apply_relu<<<g, 256>>>(p_t, bn_g + i*DIM, bn_b + i*DIM, p_bn, p_qsp);
        }
        {
            dim3 g(HW/128, (3*DIM)/64, BATCH);
            gemm_bf3<<<g, 256>>>(p_qw + (size_t)i*64*3*DIM, p_qsp, 1, nullptr, nullptr,
                                 p_qkv, 0, 3*DIM, DIM);
        }
        {
            dim3 g(HW/32, HEADS, BATCH);
            dim3 blk(32, CH);
            attn_core<<<g, blk>>>(p_qkv, p_asp);
        }
        {
            dim3 g(HW/128, DIM/64, BATCH);
            gemm_bf3<<<g, 256>>>(p_fw + (size_t)i*64*DIM, p_asp, 1, fc_b + i*DIM, p_bn,
                                 p_hsp, 1, DIM, DIM);
        }
    }

    {
        dim3 g(HW/128, COUT/64, BATCH);
        gemm_bf3<<<g, 256>>>(p_wo, p_hsp, 1, b_out, nullptr, out, 0, COUT, DIM);
    }
}

// round 10
// speedup vs baseline: 1.4362x; 1.0068x over previous
#include <cuda_runtime.h>
#include <cuda_bf16.h>
#include <cstdint>
#include <cstddef>

#define BATCH 2
#define DIM 128
#define CIN 64
#define COUT 64
#define HH 96
#define WW 96
#define HW (HH*WW)           // 9216
#define HEADS 8
#define CH 16
#define DEPTH 4
#define NIDX (BATCH*HH)      // 192 (b,y) slots for bn partials

// ---------------- scratch (device globals) ----------------
__device__ __align__(16) float g_t  [BATCH*DIM*HW];   // conv out (fp32, pre-BN)
__device__ __align__(16) float g_bn [BATCH*DIM*HW];   // bn+relu out (fp32 residual)
__device__ __align__(16) float g_qkv[BATCH*3*DIM*HW];
__device__ __align__(16) uint2 g_hsp[BATCH*64*HW];    // split h   (conv / out-proj B)
__device__ __align__(16) uint2 g_qsp[BATCH*64*HW];    // split bn  (qkv B)
__device__ __align__(16) uint2 g_asp[BATCH*64*HW];    // split att (fc B)
__device__ float g_ps[DIM*NIDX];
__device__ float g_pq[DIM*NIDX];
// packed split weights: uint2 {hi,lo}, layout [K/2][M]
__device__ uint2 g_cw[DEPTH*9*64*DIM];   // [d][tap][ic2][oc]
__device__ uint2 g_qw[DEPTH*64*3*DIM];
__device__ uint2 g_fw[DEPTH*64*DIM];
__device__ uint2 g_wi[32*DIM];
__device__ uint2 g_wo[64*COUT];

__device__ __forceinline__ void split2(float x0, float x1, uint32_t& hi, uint32_t& lo)
{
    __nv_bfloat16 h0 = __float2bfloat16(x0);
    __nv_bfloat16 h1 = __float2bfloat16(x1);
    float l0f = x0 - __bfloat162float(h0);
    float l1f = x1 - __bfloat162float(h1);
    __nv_bfloat162 hh = __halves2bfloat162(h0, h1);
    __nv_bfloat162 ll = __halves2bfloat162(__float2bfloat16(l0f), __float2bfloat16(l1f));
    hi = *reinterpret_cast<uint32_t*>(&hh);
    lo = *reinterpret_cast<uint32_t*>(&ll);
}

__device__ __forceinline__ void mma_bf16(float c[4],
    uint32_t a0, uint32_t a1, uint32_t a2, uint32_t a3, uint32_t b0, uint32_t b1)
{
    asm volatile(
        "mma.sync.aligned.m16n8k16.row.col.f32.bf16.bf16.f32 "
        "{%0,%1,%2,%3}, {%4,%5,%6,%7}, {%8,%9}, {%0,%1,%2,%3};"
        : "+f"(c[0]), "+f"(c[1]), "+f"(c[2]), "+f"(c[3])
        : "r"(a0), "r"(a1), "r"(a2), "r"(a3), "r"(b0), "r"(b1));
}

// ---------------- unified weight prep (single launch) ----------------
#define NC (DEPTH*9*64*DIM)
#define NQ (DEPTH*64*3*DIM)
#define NF (DEPTH*64*DIM)
#define NI (32*DIM)
#define NO (64*COUT)
__global__ void prep_all(const float* __restrict__ conv_w, const float* __restrict__ qkv_w,
                         const float* __restrict__ fc_w, const float* __restrict__ w_in,
                         const float* __restrict__ w_out)
{
    int i = blockIdx.x*256 + threadIdx.x;
    float x0, x1; uint2* dst;
    if (i < NC) {
        int oc = i & 127; int r = i >> 7; int ic2 = r & 63; r >>= 6;
        int tap = r % 9, d = r / 9;
        size_t base = ((size_t)(d*DIM + oc)*DIM + 2*ic2)*9 + tap;
        x0 = conv_w[base]; x1 = conv_w[base + 9]; dst = &g_cw[i];
    } else if (i < NC+NQ) {
        int j = i - NC; int d = j / (64*384); int l = j % (64*384);
        int k2 = l / 384, m = l % 384;
        x0 = qkv_w[((size_t)d*384 + m)*DIM + 2*k2];
        x1 = qkv_w[((size_t)d*384 + m)*DIM + 2*k2 + 1];
        dst = &g_qw[j];
    } else if (i < NC+NQ+NF) {
        int j = i - NC - NQ; int d = j / (64*DIM); int l = j % (64*DIM);
        int k2 = l / DIM, m = l % DIM;
        x0 = fc_w[((size_t)d*DIM + m)*DIM + 2*k2];
        x1 = fc_w[((size_t)d*DIM + m)*DIM + 2*k2 + 1];
        dst = &g_fw[j];
    } else if (i < NC+NQ+NF+NI) {
        int j = i - NC - NQ - NF; int k2 = j / DIM, m = j % DIM;
        x0 = w_in[(size_t)m*CIN + 2*k2]; x1 = w_in[(size_t)m*CIN + 2*k2 + 1];
        dst = &g_wi[j];
    } else if (i < NC+NQ+NF+NI+NO) {
        int j = i - NC - NQ - NF - NI; int k2 = j / COUT, m = j % COUT;
        x0 = w_out[(size_t)m*DIM + 2*k2]; x1 = w_out[(size_t)m*DIM + 2*k2 + 1];
        dst = &g_wo[j];
    } else return;
    uint32_t hi, lo; split2(x0, x1, hi, lo);
    *dst = make_uint2(hi, lo);
}

// ---------------- unified bf16x3 GEMM (2-stage pipelined, 64m x 128n, uint2 smem) -------
__global__ void gemm_bf3(const uint2* __restrict__ W, const void* __restrict__ Bin, int bsplit,
                         const float* __restrict__ bias, const float* __restrict__ res,
                         void* __restrict__ Out, int osplit, int Mtot, int K)
{
    const int b  = blockIdx.z;
    const int m0 = blockIdx.y * 64, n0 = blockIdx.x * 128;

    __shared__ uint2 As2[2][8][76];     // pad 76: conflict-free LDS.64
    __shared__ uint2 Bs2[2][8][140];    // pad 140 (== 12 mod 16)

    const int tid  = threadIdx.x;
    const int warp = tid >> 5, lane = tid & 31;
    const int wm = warp >> 2, wn = warp & 3;
    const int g = lane >> 2, t = lane & 3;
    const int tt0 = tid >> 6, mcol = tid & 63;

    const uint2* Bsp = (const uint2*)Bin + (size_t)b*(K/2)*HW;
    const float* Bf  = (const float*)Bin + (size_t)b*K*HW;

    const int nk = K/16;
    float acc[2][4][4] = {};

    uint2 ra0, ra1, rb[4];
    float f0[4], f1[4];

#define G_LOAD(c) do { \
        ra0 = W[(size_t)((c)*8 + tt0)*Mtot + m0 + mcol]; \
        ra1 = W[(size_t)((c)*8 + tt0 + 4)*Mtot + m0 + mcol]; \
        if (bsplit) { \
            _Pragma("unroll") \
            for (int j_ = 0; j_ < 4; j_++) { \
                int i_ = tid + j_*256; int tt_ = i_ >> 7; int n_ = i_ & 127; \
                rb[j_] = Bsp[(size_t)((c)*8 + tt_)*HW + n0 + n_]; \
            } \
        } else { \
            _Pragma("unroll") \
            for (int j_ = 0; j_ < 4; j_++) { \
                int i_ = tid + j_*256; int tt_ = i_ >> 7; int n_ = i_ & 127; \
                const float* xp_ = &Bf[(size_t)((c)*16 + 2*tt_)*HW + n0 + n_]; \
                f0[j_] = xp_[0]; f1[j_] = xp_[HW]; \
            } \
        } \
    } while(0)

#define G_STORE(s) do { \
        As2[s][tt0][mcol]   = ra0; \
        As2[s][tt0+4][mcol] = ra1; \
        _Pragma("unroll") \
        for (int j_ = 0; j_ < 4; j_++) { \
            int i_ = tid + j_*256; int tt_ = i_ >> 7; int n_ = i_ & 127; \
            if (bsplit) { \
                Bs2[s][tt_][n_] = rb[j_]; \
            } else { \
                uint32_t hi_, lo_; split2(f0[j_], f1[j_], hi_, lo_); \
                Bs2[s][tt_][n_] = make_uint2(hi_, lo_); \
            } \
        } \
    } while(0)

    G_LOAD(0); G_STORE(0);
    __syncthreads();
    for (int c = 0; c < nk; c++) {
        const int cur = c & 1;
        if (c + 1 < nk) G_LOAD(c + 1);

        uint32_t ah[2][4], al[2][4];
        #pragma unroll
        for (int mt = 0; mt < 2; mt++) {
            int mrow = wm*32 + mt*16 + g;
            uint2 a00 = As2[cur][t  ][mrow], a01 = As2[cur][t  ][mrow+8];
            uint2 a10 = As2[cur][t+4][mrow], a11 = As2[cur][t+4][mrow+8];
            ah[mt][0] = a00.x; ah[mt][1] = a01.x; ah[mt][2] = a10.x; ah[mt][3] = a11.x;
            al[mt][0] = a00.y; al[mt][1] = a01.y; al[mt][2] = a10.y; al[mt][3] = a11.y;
        }
        #pragma unroll
        for (int nt = 0; nt < 4; nt++) {
            int col = wn*32 + nt*8 + g;
            uint2 b0 = Bs2[cur][t][col], b1 = Bs2[cur][t+4][col];
            #pragma unroll
            for (int mt = 0; mt < 2; mt++) {
                mma_bf16(acc[mt][nt], ah[mt][0], ah[mt][1], ah[mt][2], ah[mt][3], b0.x, b1.x);
                mma_bf16(acc[mt][nt], ah[mt][0], ah[mt][1], ah[mt][2], ah[mt][3], b0.y, b1.y);
                mma_bf16(acc[mt][nt], al[mt][0], al[mt][1], al[mt][2], al[mt][3], b0.x, b1.x);
            }
        }
        if (c + 1 < nk) G_STORE(cur ^ 1);
        __syncthreads();
    }
#undef G_LOAD
#undef G_STORE

    const float* Rb = res ? res + (size_t)b*Mtot*HW : nullptr;

    #pragma unroll
    for (int mt = 0; mt < 2; mt++) {
        const int row0 = m0 + wm*32 + mt*16 + g;
        const float b0v = bias ? bias[row0]     : 0.f;
        const float b1v = bias ? bias[row0 + 8] : 0.f;
        #pragma unroll
        for (int nt = 0; nt < 4; nt++) {
            int col = n0 + wn*32 + nt*8 + 2*t;
            float v00 = acc[mt][nt][0] + b0v, v01 = acc[mt][nt][1] + b0v;
            float v10 = acc[mt][nt][2] + b1v, v11 = acc[mt][nt][3] + b1v;
            if (Rb) {
                float2 r0 = *(const float2*)&Rb[(size_t)row0*HW + col];
                float2 r1 = *(const float2*)&Rb[(size_t)(row0+8)*HW + col];
                v00 += r0.x; v01 += r0.y; v10 += r1.x; v11 += r1.y;
            }
            if (!osplit) {
                float* Yb = (float*)Out + (size_t)b*Mtot*HW;
                *(float2*)&Yb[(size_t)row0*HW + col]     = make_float2(v00, v01);
                *(float2*)&Yb[(size_t)(row0+8)*HW + col] = make_float2(v10, v11);
            } else {
                float p00 = __shfl_xor_sync(0xffffffffu, v00, 4);
                float p01 = __shfl_xor_sync(0xffffffffu, v01, 4);
                float p10 = __shfl_xor_sync(0xffffffffu, v10, 4);
                float p11 = __shfl_xor_sync(0xffffffffu, v11, 4);
                if (!(g & 1)) {
                    uint2* Osp = (uint2*)Out + (size_t)b*(Mtot/2)*HW;
                    int c2 = row0 >> 1;
                    uint32_t h0,l0,h1,l1;
                    split2(v00, p00, h0, l0); split2(v01, p01, h1, l1);
                    *(uint4*)&Osp[(size_t)c2*HW + col] = make_uint4(h0,l0,h1,l1);
                    split2(v10, p10, h0, l0); split2(v11, p11, h1, l1);
                    *(uint4*)&Osp[(size_t)(c2+4)*HW + col] = make_uint4(h0,l0,h1,l1);
                }
            }
        }
    }
}

// ---------------- dilated 3x3 conv (bf16x3, pipelined, uint2 smem, 64m x 96n) ----------
__global__ void conv3x3_bf3(const uint2* __restrict__ Bsp, const uint2* __restrict__ CW,
                            const float* __restrict__ bias, float* __restrict__ Y, int d)
{
    const int m0 = blockIdx.x * 64;
    const int y  = blockIdx.y;
    const int b  = blockIdx.z;
    const uint2* Xb = Bsp + (size_t)b*64*HW;

    __shared__ uint2 As2[2][8][76];
    __shared__ uint2 Bs2[2][8][108];   // pad 108 (== 12 mod 16)
    __shared__ float sS[2][64], sQ[2][64];

    const int tid  = threadIdx.x;
    const int warp = tid >> 5, lane = tid & 31;
    const int wm = warp >> 1, wn = warp & 1;
    const int g = lane >> 2, t = lane & 3;
    const int tt0 = tid >> 6, mcol = tid & 63;

    int tidx[9], txs[9], roff[9], nv = 0;
    #pragma unroll
    for (int tap = 0; tap < 9; tap++) {
        int dy = tap/3 - 1, dx = tap%3 - 1;
        int yy = y + dy*d;
        if (yy >= 0 && yy < HH) {
            tidx[nv] = tap; txs[nv] = dx*d; roff[nv] = yy*WW; nv++;
        }
    }
    const int nchunks = nv * 8;

    float acc[6][4] = {};
    uint2 ra0, ra1, rb[3];

#define C_LOAD(cc) do { \
        int tv_ = (cc) >> 3, kc_ = (cc) & 7; int icb_ = kc_*8; \
        const uint2* Wt_ = CW + (size_t)tidx[tv_]*64*DIM; \
        ra0 = Wt_[(size_t)(icb_ + tt0)*DIM + m0 + mcol]; \
        ra1 = Wt_[(size_t)(icb_ + tt0 + 4)*DIM + m0 + mcol]; \
        const uint2* Xr_ = Xb + roff[tv_]; int sh_ = txs[tv_]; \
        _Pragma("unroll") \
        for (int j_ = 0; j_ < 3; j_++) { \
            int i_ = tid + j_*256; int tt_ = i_ / 96; int n_ = i_ - 96*tt_; \
            int xx_ = n_ + sh_; \
            rb[j_] = (xx_ >= 0 && xx_ < WW) ? Xr_[(size_t)(icb_ + tt_)*HW + xx_] \
                                            : make_uint2(0u, 0u); \
        } \
    } while(0)

#define C_STORE(s) do { \
        As2[s][tt0][mcol]   = ra0; \
        As2[s][tt0+4][mcol] = ra1; \
        _Pragma("unroll") \
        for (int j_ = 0; j_ < 3; j_++) { \
            int i_ = tid + j_*256; int tt_ = i_ / 96; int n_ = i_ - 96*tt_; \
            Bs2[s][tt_][n_] = rb[j_]; \
        } \
    } while(0)

    C_LOAD(0); C_STORE(0);
    __syncthreads();
    for (int cc = 0; cc < nchunks; cc++) {
        const int cur = cc & 1;
        if (cc + 1 < nchunks) C_LOAD(cc + 1);

        const int mrow = wm*16 + g;
        uint2 a00 = As2[cur][t  ][mrow], a01 = As2[cur][t  ][mrow+8];
        uint2 a10 = As2[cur][t+4][mrow], a11 = As2[cur][t+4][mrow+8];
        #pragma unroll
        for (int nt = 0; nt < 6; nt++) {
            int col = wn*48 + nt*8 + g;
            uint2 b0 = Bs2[cur][t][col], b1 = Bs2[cur][t+4][col];
            mma_bf16(acc[nt], a00.x, a01.x, a10.x, a11.x, b0.x, b1.x);
            mma_bf16(acc[nt], a00.x, a01.x, a10.x, a11.x, b0.y, b1.y);
            mma_bf16(acc[nt], a00.y, a01.y, a10.y, a11.y, b0.x, b1.x);
        }
        if (cc + 1 < nchunks) C_STORE(cur ^ 1);
        __syncthreads();
    }
#undef C_LOAD
#undef C_STORE

    float* Yb = Y + (size_t)b*DIM*HW + (size_t)y*WW;
    const int row0 = m0 + wm*16 + g;
    const float b0v = bias[row0], b1v = bias[row0 + 8];
    float s0 = 0.f, q0 = 0.f, s1 = 0.f, q1 = 0.f;
    #pragma unroll
    for (int nt = 0; nt < 6; nt++) {
        int col = wn*48 + nt*8 + 2*t;
        float v00 = acc[nt][0] + b0v, v01 = acc[nt][1] + b0v;
        float v10 = acc[nt][2] + b1v, v11 = acc[nt][3] + b1v;
        *(float2*)&Yb[(size_t)row0*HW + col]     = make_float2(v00, v01);
        *(float2*)&Yb[(size_t)(row0+8)*HW + col] = make_float2(v10, v11);
        s0 += v00 + v01; q0 += v00*v00 + v01*v01;
        s1 += v10 + v11; q1 += v10*v10 + v11*v11;
    }
    #pragma unroll
    for (int o = 1; o <= 2; o <<= 1) {
        s0 += __shfl_xor_sync(0xffffffffu, s0, o);
        q0 += __shfl_xor_sync(0xffffffffu, q0, o);
        s1 += __shfl_xor_sync(0xffffffffu, s1, o);
        q1 += __shfl_xor_sync(0xffffffffu, q1, o);
    }
    if (t == 0) {
        int lr = wm*16 + g;
        sS[wn][lr] = s0;   sQ[wn][lr] = q0;
        sS[wn][lr+8] = s1; sQ[wn][lr+8] = q1;
    }
    __syncthreads();
    if (tid < 64) {
        int idx = b*HH + y;
        g_ps[(size_t)(m0+tid)*NIDX + idx] = sS[0][tid] + sS[1][tid];
        g_pq[(size_t)(m0+tid)*NIDX + idx] = sQ[0][tid] + sQ[1][tid];
    }
}

// ---------------- bn apply + relu (inline stats; 2304=9*256 so block has one c2) ----------------
__global__ void bn_apply_relu(const float* __restrict__ X, const float* __restrict__ gam,
                              const float* __restrict__ beta, float* __restrict__ Yf,
                              uint2* __restrict__ Ysp)
{
    const int b = blockIdx.y;
    int i = blockIdx.x*256 + threadIdx.x;
    int c2 = i / (HW/4);
    int p  = (i - c2*(HW/4)) * 4;
    int c0 = 2*c2, c1 = 2*c2 + 1;

    __shared__ float st[4];
    __shared__ float rs[4][8];
    {
        float s0=0.f, q0=0.f, s1=0.f, q1=0.f;
        int tt = threadIdx.x;
        if (tt < NIDX) {
            s0 = g_ps[(size_t)c0*NIDX + tt]; q0 = g_pq[(size_t)c0*NIDX + tt];
            s1 = g_ps[(size_t)c1*NIDX + tt]; q1 = g_pq[(size_t)c1*NIDX + tt];
        }
        #pragma unroll
        for (int o = 16; o > 0; o >>= 1) {
            s0 += __shfl_xor_sync(0xffffffffu, s0, o);
            q0 += __shfl_xor_sync(0xffffffffu, q0, o);
            s1 += __shfl_xor_sync(0xffffffffu, s1, o);
            q1 += __shfl_xor_sync(0xffffffffu, q1, o);
        }
        int w = threadIdx.x >> 5;
        if ((threadIdx.x & 31) == 0) {
            rs[0][w] = s0; rs[1][w] = q0; rs[2][w] = s1; rs[3][w] = q1;
        }
        __syncthreads();
        if (threadIdx.x == 0) {
            float S0=0,Q0=0,S1=0,Q1=0;
            #pragma unroll
            for (int k = 0; k < 8; k++) { S0+=rs[0][k]; Q0+=rs[1][k]; S1+=rs[2][k]; Q1+=rs[3][k]; }
            const float invN = 1.f / (BATCH*HW);
            float mm0 = S0*invN, mm1 = S1*invN;
            st[0] = mm0; st[1] = rsqrtf(Q0*invN - mm0*mm0 + 1e-5f);
            st[2] = mm1; st[3] = rsqrtf(Q1*invN - mm1*mm1 + 1e-5f);
        }
        __syncthreads();
    }
    float m0 = st[0], r0 = st[1], m1 = st[2], r1 = st[3];
    float ga0 = gam[c0], be0 = beta[c0], ga1 = gam[c1], be1 = beta[c1];

    const float* Xb = X + (size_t)b*DIM*HW;
    float* Yb = Yf + (size_t)b*DIM*HW;
    uint2* Sb = Ysp + (size_t)b*64*HW;

    float4 a = *(const float4*)&Xb[(size_t)c0*HW + p];
    float4 c = *(const float4*)&Xb[(size_t)c1*HW + p];
    float y0x = fmaxf((a.x-m0)*r0*ga0+be0, 0.f), y0y = fmaxf((a.y-m0)*r0*ga0+be0, 0.f);
    float y0z = fmaxf((a.z-m0)*r0*ga0+be0, 0.f), y0w = fmaxf((a.w-m0)*r0*ga0+be0, 0.f);
    float y1x = fmaxf((c.x-m1)*r1*ga1+be1, 0.f), y1y = fmaxf((c.y-m1)*r1*ga1+be1, 0.f);
    float y1z = fmaxf((c.z-m1)*r1*ga1+be1, 0.f), y1w = fmaxf((c.w-m1)*r1*ga1+be1, 0.f);

    *(float4*)&Yb[(size_t)c0*HW + p] = make_float4(y0x, y0y, y0z, y0w);
    *(float4*)&Yb[(size_t)c1*HW + p] = make_float4(y1x, y1y, y1z, y1w);

    uint32_t h0,l0,h1,l1,h2,l2,h3,l3;
    split2(y0x, y1x, h0, l0); split2(y0y, y1y, h1, l1);
    split2(y0z, y1z, h2, l2); split2(y0w, y1w, h3, l3);
    uint4* dst = (uint4*)&Sb[(size_t)c2*HW + p];
    dst[0] = make_uint4(h0, l0, h1, l1);
    dst[1] = make_uint4(h2, l2, h3, l3);
}

// ---------------- local channel self-attention (split epilogue) ----------------
__global__ void attn_core(const float* __restrict__ QKV, uint2* __restrict__ OUT)
{
    const int b = blockIdx.z, h = blockIdx.y;
    const int p0 = blockIdx.x * 32;
    const int y  = p0 / WW, x0 = p0 % WW;
    const float* Qb = QKV + ((size_t)b*3*DIM + h*CH)*HW;
    const float* Kb = Qb + (size_t)DIM*HW;
    const float* Vb = Qb + (size_t)2*DIM*HW;

    __shared__ float qs[CH][3][34];
    __shared__ float ks[CH][3][34];
    __shared__ float vs[CH][3][34];
    __shared__ float sato[CH][33];

    const int tid = threadIdx.y*32 + threadIdx.x;
    for (int i = tid; i < CH*3*34; i += 512) {
        int xi = i % 34; int rr = i / 34; int yi = rr % 3; int c = rr / 3;
        int yy = y + yi - 1, xx = x0 + xi - 1;
        bool ok = (yy >= 0 && yy < HH && xx >= 0 && xx < WW);
        int o = c*HW + yy*WW + xx;
        qs[c][yi][xi] = ok ? Qb[o] : 0.f;
        ks[c][yi][xi] = ok ? Kb[o] : 0.f;
        vs[c][yi][xi] = ok ? Vb[o] : 0.f;
    }
    __syncthreads();

    const int nn = threadIdx.y, lx = threadIdx.x;
    float qr[9];
    #pragma unroll
    for (int t = 0; t < 9; t++) qr[t] = qs[nn][t/3][lx + t%3] * 0.25f;

    float dots[CH], vsum[CH];
    #pragma unroll
    for (int m = 0; m < CH; m++) {
        float dv = 0.f, sv = 0.f;
        #pragma unroll
        for (int t = 0; t < 9; t++) {
            dv += qr[t] * ks[m][t/3][lx + t%3];
            sv += vs[m][t/3][lx + t%3];
        }
        dots[m] = dv; vsum[m] = sv;
    }
    float mx = dots[0];
    #pragma unroll
    for (int m = 1; m < CH; m++) mx = fmaxf(mx, dots[m]);
    float s = 0.f;
    #pragma unroll
    for (int m = 0; m < CH; m++) { dots[m] = __expf(dots[m]-mx); s += dots[m]; }
    float o = 0.f;
    #pragma unroll
    for (int m = 0; m < CH; m++) o += dots[m]*vsum[m];
    sato[nn][lx] = o / s;
    __syncthreads();

    if (nn < 8) {
        float v0 = sato[2*nn][lx], v1 = sato[2*nn+1][lx];
        uint32_t hi, lo; split2(v0, v1, hi, lo);
        OUT[(size_t)b*64*HW + (size_t)(h*8 + nn)*HW + p0 + lx] = make_uint2(hi, lo);
    }
}

// ---------------- host orchestration ----------------
extern "C" void kernel_launch(void* const* d_in, const int* in_sizes, int n_in,
                              void* d_out, int out_size)
{
    const float* x      = (const float*)d_in[0];
    const float* w_in   = (const float*)d_in[1];
    const float* b_in   = (const float*)d_in[2];
    const float* conv_w = (const float*)d_in[3];
    const float* conv_b = (const float*)d_in[4];
    const float* bn_g   = (const float*)d_in[5];
    const float* bn_b   = (const float*)d_in[6];
    const float* qkv_w  = (const float*)d_in[7];
    const float* fc_w   = (const float*)d_in[8];
    const float* fc_b   = (const float*)d_in[9];
    const float* w_out  = (const float*)d_in[10];
    const float* b_out  = (const float*)d_in[11];
    float* out = (float*)d_out;

    float *p_t, *p_bn, *p_qkv;
    uint2 *p_hsp, *p_qsp, *p_asp, *p_cw, *p_qw, *p_fw, *p_wi, *p_wo;
    cudaGetSymbolAddress((void**)&p_t,   g_t);
    cudaGetSymbolAddress((void**)&p_bn,  g_bn);
    cudaGetSymbolAddress((void**)&p_qkv, g_qkv);
    cudaGetSymbolAddress((void**)&p_hsp, g_hsp);
    cudaGetSymbolAddress((void**)&p_qsp, g_qsp);
    cudaGetSymbolAddress((void**)&p_asp, g_asp);
    cudaGetSymbolAddress((void**)&p_cw,  g_cw);
    cudaGetSymbolAddress((void**)&p_qw,  g_qw);
    cudaGetSymbolAddress((void**)&p_fw,  g_fw);
    cudaGetSymbolAddress((void**)&p_wi,  g_wi);
    cudaGetSymbolAddress((void**)&p_wo,  g_wo);

    prep_all<<<(NC+NQ+NF+NI+NO + 255)/256, 256>>>(conv_w, qkv_w, fc_w, w_in, w_out);

    // input projection 64 -> 128, split output into g_hsp
    {
        dim3 g(HW/128, DIM/64, BATCH);
        gemm_bf3<<<g, 256>>>(p_wi, x, 0, b_in, nullptr, p_hsp, 1, DIM, CIN);
    }

    for (int i = 0; i < DEPTH; i++) {
        const int d = 1 << i;
        {   // dilated conv (one row per block, as in R6)
            dim3 g(2, HH, BATCH);
            conv3x3_bf3<<<g, 256>>>(p_hsp, p_cw + (size_t)i*9*64*DIM,
                                    conv_b + i*DIM, p_t, d);
        }
        {
            dim3 g((64*HW/4)/256, BATCH);
            bn_apply_relu<<<g, 256>>>(p_t, bn_g + i*DIM, bn_b + i*DIM, p_bn, p_qsp);
        }
        {
            dim3 g(HW/128, (3*DIM)/64, BATCH);
            gemm_bf3<<<g, 256>>>(p_qw + (size_t)i*64*3*DIM, p_qsp, 1, nullptr, nullptr,
                                 p_qkv, 0, 3*DIM, DIM);
        }
        {
            dim3 g(HW/32, HEADS, BATCH);
            dim3 blk(32, CH);
            attn_core<<<g, blk>>>(p_qkv, p_asp);
        }
        {
            dim3 g(HW/128, DIM/64, BATCH);
            gemm_bf3<<<g, 256>>>(p_fw + (size_t)i*64*DIM, p_asp, 1, fc_b + i*DIM, p_bn,
                                 p_hsp, 1, DIM, DIM);
        }
    }

    {
        dim3 g(HW/128, COUT/64, BATCH);
        gemm_bf3<<<g, 256>>>(p_wo, p_hsp, 1, b_out, nullptr, out, 0, COUT, DIM);
    }
}

// round 11
// speedup vs baseline: 1.7080x; 1.1892x over previous
#include <cuda_runtime.h>
#include <cuda_fp16.h>
#include <cstdint>
#include <cstddef>

#define BATCH 2
#define DIM 128
#define CIN 64
#define COUT 64
#define HH 96
#define WW 96
#define HW (HH*WW)           // 9216
#define HEADS 8
#define CH 16
#define DEPTH 4
#define NIDX (BATCH*HH)      // 192 (b,y) slots for bn partials

// ---------------- scratch (device globals) ----------------
__device__ __align__(16) float g_t  [BATCH*DIM*HW];   // conv out (fp32, pre-BN)
__device__ __align__(16) float g_bn [BATCH*DIM*HW];   // bn+relu out (fp32 residual)
__device__ __align__(16) float g_qkv[BATCH*3*DIM*HW];
__device__ __align__(16) uint32_t g_hsp[BATCH*64*HW]; // half2 h   (conv / out-proj B)
__device__ __align__(16) uint32_t g_qsp[BATCH*64*HW]; // half2 bn  (qkv B)
__device__ __align__(16) uint32_t g_asp[BATCH*64*HW]; // half2 att (fc B)
__device__ float g_ps[DIM*NIDX];
__device__ float g_pq[DIM*NIDX];
// weights: exact fp16 split, uint2 {hi2, lo2}, layout [K/2][M]
__device__ uint2 g_cw[DEPTH*9*64*DIM];   // [d][tap][ic2][oc]
__device__ uint2 g_qw[DEPTH*64*3*DIM];
__device__ uint2 g_fw[DEPTH*64*DIM];
__device__ uint2 g_wi[32*DIM];
__device__ uint2 g_wo[64*COUT];

__device__ __forceinline__ uint32_t h2(float a, float b)
{
    __half2 h = __floats2half2_rn(a, b);
    return *reinterpret_cast<uint32_t*>(&h);
}
__device__ __forceinline__ void splitw(float x0, float x1, uint32_t& hi, uint32_t& lo)
{
    __half h0 = __float2half_rn(x0);
    __half h1 = __float2half_rn(x1);
    float l0 = x0 - __half2float(h0);
    float l1 = x1 - __half2float(h1);
    __half2 hh = __halves2half2(h0, h1);
    __half2 ll = __floats2half2_rn(l0, l1);
    hi = *reinterpret_cast<uint32_t*>(&hh);
    lo = *reinterpret_cast<uint32_t*>(&ll);
}

__device__ __forceinline__ void mma_f16(float c[4],
    uint32_t a0, uint32_t a1, uint32_t a2, uint32_t a3, uint32_t b0, uint32_t b1)
{
    asm volatile(
        "mma.sync.aligned.m16n8k16.row.col.f32.f16.f16.f32 "
        "{%0,%1,%2,%3}, {%4,%5,%6,%7}, {%8,%9}, {%0,%1,%2,%3};"
        : "+f"(c[0]), "+f"(c[1]), "+f"(c[2]), "+f"(c[3])
        : "r"(a0), "r"(a1), "r"(a2), "r"(a3), "r"(b0), "r"(b1));
}

// ---------------- unified weight prep (single launch) ----------------
#define NC (DEPTH*9*64*DIM)
#define NQ (DEPTH*64*3*DIM)
#define NF (DEPTH*64*DIM)
#define NI (32*DIM)
#define NO (64*COUT)
__global__ void prep_all(const float* __restrict__ conv_w, const float* __restrict__ qkv_w,
                         const float* __restrict__ fc_w, const float* __restrict__ w_in,
                         const float* __restrict__ w_out)
{
    int i = blockIdx.x*256 + threadIdx.x;
    float x0, x1; uint2* dst;
    if (i < NC) {
        int oc = i & 127; int r = i >> 7; int ic2 = r & 63; r >>= 6;
        int tap = r % 9, d = r / 9;
        size_t base = ((size_t)(d*DIM + oc)*DIM + 2*ic2)*9 + tap;
        x0 = conv_w[base]; x1 = conv_w[base + 9]; dst = &g_cw[i];
    } else if (i < NC+NQ) {
        int j = i - NC; int d = j / (64*384); int l = j % (64*384);
        int k2 = l / 384, m = l % 384;
        x0 = qkv_w[((size_t)d*384 + m)*DIM + 2*k2];
        x1 = qkv_w[((size_t)d*384 + m)*DIM + 2*k2 + 1];
        dst = &g_qw[j];
    } else if (i < NC+NQ+NF) {
        int j = i - NC - NQ; int d = j / (64*DIM); int l = j % (64*DIM);
        int k2 = l / DIM, m = l % DIM;
        x0 = fc_w[((size_t)d*DIM + m)*DIM + 2*k2];
        x1 = fc_w[((size_t)d*DIM + m)*DIM + 2*k2 + 1];
        dst = &g_fw[j];
    } else if (i < NC+NQ+NF+NI) {
        int j = i - NC - NQ - NF; int k2 = j / DIM, m = j % DIM;
        x0 = w_in[(size_t)m*CIN + 2*k2]; x1 = w_in[(size_t)m*CIN + 2*k2 + 1];
        dst = &g_wi[j];
    } else if (i < NC+NQ+NF+NI+NO) {
        int j = i - NC - NQ - NF - NI; int k2 = j / COUT, m = j % COUT;
        x0 = w_out[(size_t)m*DIM + 2*k2]; x1 = w_out[(size_t)m*DIM + 2*k2 + 1];
        dst = &g_wo[j];
    } else return;
    uint32_t hi, lo; splitw(x0, x1, hi, lo);
    *dst = make_uint2(hi, lo);
}

// ---------------- fp16x2 GEMM (2-stage pipelined, 64m x 128n block) ----------------
// W: [K/2][Mtot] uint2 {hi2,lo2}. B: half2 [K/2][HW] (bsplit=1) or fp32 [K][HW].
// Out: fp32 [Mtot][HW] (osplit=0) or half2 [Mtot/2][HW] (osplit=1).
__global__ void gemm_f16(const uint2* __restrict__ W, const void* __restrict__ Bin, int bsplit,
                         const float* __restrict__ bias, const float* __restrict__ res,
                         void* __restrict__ Out, int osplit, int Mtot, int K)
{
    const int b  = blockIdx.z;
    const int m0 = blockIdx.y * 64, n0 = blockIdx.x * 128;

    __shared__ uint32_t As[2][2][8][72];
    __shared__ uint32_t Bs[2][8][136];

    const int tid  = threadIdx.x;
    const int warp = tid >> 5, lane = tid & 31;
    const int wm = warp >> 2, wn = warp & 3;
    const int g = lane >> 2, t = lane & 3;
    const int tt0 = tid >> 6, mcol = tid & 63;

    const uint32_t* Bsp = (const uint32_t*)Bin + (size_t)b*(K/2)*HW;
    const float*    Bf  = (const float*)Bin + (size_t)b*K*HW;

    const int nk = K/16;
    float acc[2][4][4] = {};

    uint2 ra0, ra1;
    uint32_t rb[4];
    float f0[4], f1[4];

#define G_LOAD(c) do { \
        ra0 = W[(size_t)((c)*8 + tt0)*Mtot + m0 + mcol]; \
        ra1 = W[(size_t)((c)*8 + tt0 + 4)*Mtot + m0 + mcol]; \
        if (bsplit) { \
            _Pragma("unroll") \
            for (int j_ = 0; j_ < 4; j_++) { \
                int i_ = tid + j_*256; int tt_ = i_ >> 7; int n_ = i_ & 127; \
                rb[j_] = Bsp[(size_t)((c)*8 + tt_)*HW + n0 + n_]; \
            } \
        } else { \
            _Pragma("unroll") \
            for (int j_ = 0; j_ < 4; j_++) { \
                int i_ = tid + j_*256; int tt_ = i_ >> 7; int n_ = i_ & 127; \
                const float* xp_ = &Bf[(size_t)((c)*16 + 2*tt_)*HW + n0 + n_]; \
                f0[j_] = xp_[0]; f1[j_] = xp_[HW]; \
            } \
        } \
    } while(0)

#define G_STORE(s) do { \
        As[s][0][tt0][mcol] = ra0.x;   As[s][1][tt0][mcol] = ra0.y; \
        As[s][0][tt0+4][mcol] = ra1.x; As[s][1][tt0+4][mcol] = ra1.y; \
        _Pragma("unroll") \
        for (int j_ = 0; j_ < 4; j_++) { \
            int i_ = tid + j_*256; int tt_ = i_ >> 7; int n_ = i_ & 127; \
            Bs[s][tt_][n_] = bsplit ? rb[j_] : h2(f0[j_], f1[j_]); \
        } \
    } while(0)

    G_LOAD(0); G_STORE(0);
    __syncthreads();
    for (int c = 0; c < nk; c++) {
        const int cur = c & 1;
        if (c + 1 < nk) G_LOAD(c + 1);

        uint32_t ah[2][4], al[2][4];
        #pragma unroll
        for (int mt = 0; mt < 2; mt++) {
            int mrow = wm*32 + mt*16 + g;
            ah[mt][0] = As[cur][0][t  ][mrow]; ah[mt][1] = As[cur][0][t  ][mrow+8];
            ah[mt][2] = As[cur][0][t+4][mrow]; ah[mt][3] = As[cur][0][t+4][mrow+8];
            al[mt][0] = As[cur][1][t  ][mrow]; al[mt][1] = As[cur][1][t  ][mrow+8];
            al[mt][2] = As[cur][1][t+4][mrow]; al[mt][3] = As[cur][1][t+4][mrow+8];
        }
        #pragma unroll
        for (int nt = 0; nt < 4; nt++) {
            int col = wn*32 + nt*8 + g;
            uint32_t b0 = Bs[cur][t][col], b1 = Bs[cur][t+4][col];
            #pragma unroll
            for (int mt = 0; mt < 2; mt++) {
                mma_f16(acc[mt][nt], ah[mt][0], ah[mt][1], ah[mt][2], ah[mt][3], b0, b1);
                mma_f16(acc[mt][nt], al[mt][0], al[mt][1], al[mt][2], al[mt][3], b0, b1);
            }
        }
        if (c + 1 < nk) G_STORE(cur ^ 1);
        __syncthreads();
    }
#undef G_LOAD
#undef G_STORE

    const float* Rb = res ? res + (size_t)b*Mtot*HW : nullptr;

    #pragma unroll
    for (int mt = 0; mt < 2; mt++) {
        const int row0 = m0 + wm*32 + mt*16 + g;
        const float b0v = bias ? bias[row0]     : 0.f;
        const float b1v = bias ? bias[row0 + 8] : 0.f;
        #pragma unroll
        for (int nt = 0; nt < 4; nt++) {
            int col = n0 + wn*32 + nt*8 + 2*t;
            float v00 = acc[mt][nt][0] + b0v, v01 = acc[mt][nt][1] + b0v;
            float v10 = acc[mt][nt][2] + b1v, v11 = acc[mt][nt][3] + b1v;
            if (Rb) {
                float2 r0 = *(const float2*)&Rb[(size_t)row0*HW + col];
                float2 r1 = *(const float2*)&Rb[(size_t)(row0+8)*HW + col];
                v00 += r0.x; v01 += r0.y; v10 += r1.x; v11 += r1.y;
            }
            if (!osplit) {
                float* Yb = (float*)Out + (size_t)b*Mtot*HW;
                *(float2*)&Yb[(size_t)row0*HW + col]     = make_float2(v00, v01);
                *(float2*)&Yb[(size_t)(row0+8)*HW + col] = make_float2(v10, v11);
            } else {
                float p00 = __shfl_xor_sync(0xffffffffu, v00, 4);
                float p01 = __shfl_xor_sync(0xffffffffu, v01, 4);
                float p10 = __shfl_xor_sync(0xffffffffu, v10, 4);
                float p11 = __shfl_xor_sync(0xffffffffu, v11, 4);
                if (!(g & 1)) {
                    uint32_t* Osp = (uint32_t*)Out + (size_t)b*64*HW;
                    int c2 = row0 >> 1;
                    *(uint2*)&Osp[(size_t)c2*HW + col]     = make_uint2(h2(v00,p00), h2(v01,p01));
                    *(uint2*)&Osp[(size_t)(c2+4)*HW + col] = make_uint2(h2(v10,p10), h2(v11,p11));
                }
            }
        }
    }
}

// ---------------- dilated 3x3 conv (fp16x2, pipelined, 64m x 96n) ----------------
__global__ void conv3x3_f16(const uint32_t* __restrict__ Bsp, const uint2* __restrict__ CW,
                            const float* __restrict__ bias, float* __restrict__ Y, int d)
{
    const int m0 = blockIdx.x * 64;
    const int y  = blockIdx.y;
    const int b  = blockIdx.z;
    const uint32_t* Xb = Bsp + (size_t)b*64*HW;

    __shared__ uint32_t As[2][2][8][72];
    __shared__ uint32_t Bs[2][8][104];
    __shared__ float sS[2][64], sQ[2][64];

    const int tid  = threadIdx.x;
    const int warp = tid >> 5, lane = tid & 31;
    const int wm = warp >> 1, wn = warp & 1;
    const int g = lane >> 2, t = lane & 3;
    const int tt0 = tid >> 6, mcol = tid & 63;

    int tidx[9], txs[9], roff[9], nv = 0;
    #pragma unroll
    for (int tap = 0; tap < 9; tap++) {
        int dy = tap/3 - 1, dx = tap%3 - 1;
        int yy = y + dy*d;
        if (yy >= 0 && yy < HH) {
            tidx[nv] = tap; txs[nv] = dx*d; roff[nv] = yy*WW; nv++;
        }
    }
    const int nchunks = nv * 8;

    float acc[6][4] = {};
    uint2 ra0, ra1;
    uint32_t rb[3];

#define C_LOAD(cc) do { \
        int tv_ = (cc) >> 3, kc_ = (cc) & 7; int icb_ = kc_*8; \
        const uint2* Wt_ = CW + (size_t)tidx[tv_]*64*DIM; \
        ra0 = Wt_[(size_t)(icb_ + tt0)*DIM + m0 + mcol]; \
        ra1 = Wt_[(size_t)(icb_ + tt0 + 4)*DIM + m0 + mcol]; \
        const uint32_t* Xr_ = Xb + roff[tv_]; int sh_ = txs[tv_]; \
        _Pragma("unroll") \
        for (int j_ = 0; j_ < 3; j_++) { \
            int i_ = tid + j_*256; int tt_ = i_ / 96; int n_ = i_ - 96*tt_; \
            int xx_ = n_ + sh_; \
            rb[j_] = (xx_ >= 0 && xx_ < WW) ? Xr_[(size_t)(icb_ + tt_)*HW + xx_] : 0u; \
        } \
    } while(0)

#define C_STORE(s) do { \
        As[s][0][tt0][mcol] = ra0.x;   As[s][1][tt0][mcol] = ra0.y; \
        As[s][0][tt0+4][mcol] = ra1.x; As[s][1][tt0+4][mcol] = ra1.y; \
        _Pragma("unroll") \
        for (int j_ = 0; j_ < 3; j_++) { \
            int i_ = tid + j_*256; int tt_ = i_ / 96; int n_ = i_ - 96*tt_; \
            Bs[s][tt_][n_] = rb[j_]; \
        } \
    } while(0)

    C_LOAD(0); C_STORE(0);
    __syncthreads();
    for (int cc = 0; cc < nchunks; cc++) {
        const int cur = cc & 1;
        if (cc + 1 < nchunks) C_LOAD(cc + 1);

        const int mrow = wm*16 + g;
        uint32_t ah0 = As[cur][0][t  ][mrow], ah1 = As[cur][0][t  ][mrow+8];
        uint32_t ah2 = As[cur][0][t+4][mrow], ah3 = As[cur][0][t+4][mrow+8];
        uint32_t al0 = As[cur][1][t  ][mrow], al1 = As[cur][1][t  ][mrow+8];
        uint32_t al2 = As[cur][1][t+4][mrow], al3 = As[cur][1][t+4][mrow+8];
        #pragma unroll
        for (int nt = 0; nt < 6; nt++) {
            int col = wn*48 + nt*8 + g;
            uint32_t b0 = Bs[cur][t][col], b1 = Bs[cur][t+4][col];
            mma_f16(acc[nt], ah0, ah1, ah2, ah3, b0, b1);
            mma_f16(acc[nt], al0, al1, al2, al3, b0, b1);
        }
        if (cc + 1 < nchunks) C_STORE(cur ^ 1);
        __syncthreads();
    }
#undef C_LOAD
#undef C_STORE

    float* Yb = Y + (size_t)b*DIM*HW + (size_t)y*WW;
    const int row0 = m0 + wm*16 + g;
    const float b0v = bias[row0], b1v = bias[row0 + 8];
    float s0 = 0.f, q0 = 0.f, s1 = 0.f, q1 = 0.f;
    #pragma unroll
    for (int nt = 0; nt < 6; nt++) {
        int col = wn*48 + nt*8 + 2*t;
        float v00 = acc[nt][0] + b0v, v01 = acc[nt][1] + b0v;
        float v10 = acc[nt][2] + b1v, v11 = acc[nt][3] + b1v;
        *(float2*)&Yb[(size_t)row0*HW + col]     = make_float2(v00, v01);
        *(float2*)&Yb[(size_t)(row0+8)*HW + col] = make_float2(v10, v11);
        s0 += v00 + v01; q0 += v00*v00 + v01*v01;
        s1 += v10 + v11; q1 += v10*v10 + v11*v11;
    }
    #pragma unroll
    for (int o = 1; o <= 2; o <<= 1) {
        s0 += __shfl_xor_sync(0xffffffffu, s0, o);
        q0 += __shfl_xor_sync(0xffffffffu, q0, o);
        s1 += __shfl_xor_sync(0xffffffffu, s1, o);
        q1 += __shfl_xor_sync(0xffffffffu, q1, o);
    }
    if (t == 0) {
        int lr = wm*16 + g;
        sS[wn][lr] = s0;   sQ[wn][lr] = q0;
        sS[wn][lr+8] = s1; sQ[wn][lr+8] = q1;
    }
    __syncthreads();
    if (tid < 64) {
        int idx = b*HH + y;
        g_ps[(size_t)(m0+tid)*NIDX + idx] = sS[0][tid] + sS[1][tid];
        g_pq[(size_t)(m0+tid)*NIDX + idx] = sQ[0][tid] + sQ[1][tid];
    }
}

// ---------------- bn apply + relu (inline stats; 2304=9*256 so block has one c2) ----------------
__global__ void bn_apply_relu(const float* __restrict__ X, const float* __restrict__ gam,
                              const float* __restrict__ beta, float* __restrict__ Yf,
                              uint32_t* __restrict__ Ysp)
{
    const int b = blockIdx.y;
    int i = blockIdx.x*256 + threadIdx.x;
    int c2 = i / (HW/4);
    int p  = (i - c2*(HW/4)) * 4;
    int c0 = 2*c2, c1 = 2*c2 + 1;

    __shared__ float st[4];
    __shared__ float rs[4][8];
    {
        float s0=0.f, q0=0.f, s1=0.f, q1=0.f;
        int tt = threadIdx.x;
        if (tt < NIDX) {
            s0 = g_ps[(size_t)c0*NIDX + tt]; q0 = g_pq[(size_t)c0*NIDX + tt];
            s1 = g_ps[(size_t)c1*NIDX + tt]; q1 = g_pq[(size_t)c1*NIDX + tt];
        }
        #pragma unroll
        for (int o = 16; o > 0; o >>= 1) {
            s0 += __shfl_xor_sync(0xffffffffu, s0, o);
            q0 += __shfl_xor_sync(0xffffffffu, q0, o);
            s1 += __shfl_xor_sync(0xffffffffu, s1, o);
            q1 += __shfl_xor_sync(0xffffffffu, q1, o);
        }
        int w = threadIdx.x >> 5;
        if ((threadIdx.x & 31) == 0) {
            rs[0][w] = s0; rs[1][w] = q0; rs[2][w] = s1; rs[3][w] = q1;
        }
        __syncthreads();
        if (threadIdx.x == 0) {
            float S0=0,Q0=0,S1=0,Q1=0;
            #pragma unroll
            for (int k = 0; k < 8; k++) { S0+=rs[0][k]; Q0+=rs[1][k]; S1+=rs[2][k]; Q1+=rs[3][k]; }
            const float invN = 1.f / (BATCH*HW);
            float mm0 = S0*invN, mm1 = S1*invN;
            st[0] = mm0; st[1] = rsqrtf(Q0*invN - mm0*mm0 + 1e-5f);
            st[2] = mm1; st[3] = rsqrtf(Q1*invN - mm1*mm1 + 1e-5f);
        }
        __syncthreads();
    }
    float m0 = st[0], r0 = st[1], m1 = st[2], r1 = st[3];
    float ga0 = gam[c0], be0 = beta[c0], ga1 = gam[c1], be1 = beta[c1];

    const float* Xb = X + (size_t)b*DIM*HW;
    float* Yb = Yf + (size_t)b*DIM*HW;
    uint32_t* Sb = Ysp + (size_t)b*64*HW;

    float4 a = *(const float4*)&Xb[(size_t)c0*HW + p];
    float4 c = *(const float4*)&Xb[(size_t)c1*HW + p];
    float y0x = fmaxf((a.x-m0)*r0*ga0+be0, 0.f), y0y = fmaxf((a.y-m0)*r0*ga0+be0, 0.f);
    float y0z = fmaxf((a.z-m0)*r0*ga0+be0, 0.f), y0w = fmaxf((a.w-m0)*r0*ga0+be0, 0.f);
    float y1x = fmaxf((c.x-m1)*r1*ga1+be1, 0.f), y1y = fmaxf((c.y-m1)*r1*ga1+be1, 0.f);
    float y1z = fmaxf((c.z-m1)*r1*ga1+be1, 0.f), y1w = fmaxf((c.w-m1)*r1*ga1+be1, 0.f);

    *(float4*)&Yb[(size_t)c0*HW + p] = make_float4(y0x, y0y, y0z, y0w);
    *(float4*)&Yb[(size_t)c1*HW + p] = make_float4(y1x, y1y, y1z, y1w);

    *(uint4*)&Sb[(size_t)c2*HW + p] =
        make_uint4(h2(y0x, y1x), h2(y0y, y1y), h2(y0z, y1z), h2(y0w, y1w));
}

// ---------------- local channel self-attention (half2 epilogue) ----------------
__global__ void attn_core(const float* __restrict__ QKV, uint32_t* __restrict__ OUT)
{
    const int b = blockIdx.z, h = blockIdx.y;
    const int p0 = blockIdx.x * 32;
    const int y  = p0 / WW, x0 = p0 % WW;
    const float* Qb = QKV + ((size_t)b*3*DIM + h*CH)*HW;
    const float* Kb = Qb + (size_t)DIM*HW;
    const float* Vb = Qb + (size_t)2*DIM*HW;

    __shared__ float qs[CH][3][34];
    __shared__ float ks[CH][3][34];
    __shared__ float vs[CH][3][34];
    __shared__ float sato[CH][33];

    const int tid = threadIdx.y*32 + threadIdx.x;
    for (int i = tid; i < CH*3*34; i += 512) {
        int xi = i % 34; int rr = i / 34; int yi = rr % 3; int c = rr / 3;
        int yy = y + yi - 1, xx = x0 + xi - 1;
        bool ok = (yy >= 0 && yy < HH && xx >= 0 && xx < WW);
        int o = c*HW + yy*WW + xx;
        qs[c][yi][xi] = ok ? Qb[o] : 0.f;
        ks[c][yi][xi] = ok ? Kb[o] : 0.f;
        vs[c][yi][xi] = ok ? Vb[o] : 0.f;
    }
    __syncthreads();

    const int nn = threadIdx.y, lx = threadIdx.x;
    float qr[9];
    #pragma unroll
    for (int t = 0; t < 9; t++) qr[t] = qs[nn][t/3][lx + t%3] * 0.25f;

    float dots[CH], vsum[CH];
    #pragma unroll
    for (int m = 0; m < CH; m++) {
        float dv = 0.f, sv = 0.f;
        #pragma unroll
        for (int t = 0; t < 9; t++) {
            dv += qr[t] * ks[m][t/3][lx + t%3];
            sv += vs[m][t/3][lx + t%3];
        }
        dots[m] = dv; vsum[m] = sv;
    }
    float mx = dots[0];
    #pragma unroll
    for (int m = 1; m < CH; m++) mx = fmaxf(mx, dots[m]);
    float s = 0.f;
    #pragma unroll
    for (int m = 0; m < CH; m++) { dots[m] = __expf(dots[m]-mx); s += dots[m]; }
    float o = 0.f;
    #pragma unroll
    for (int m = 0; m < CH; m++) o += dots[m]*vsum[m];
    sato[nn][lx] = o / s;
    __syncthreads();

    if (nn < 8) {
        float v0 = sato[2*nn][lx], v1 = sato[2*nn+1][lx];
        OUT[(size_t)b*64*HW + (size_t)(h*8 + nn)*HW + p0 + lx] = h2(v0, v1);
    }
}

// ---------------- host orchestration ----------------
extern "C" void kernel_launch(void* const* d_in, const int* in_sizes, int n_in,
                              void* d_out, int out_size)
{
    const float* x      = (const float*)d_in[0];
    const float* w_in   = (const float*)d_in[1];
    const float* b_in   = (const float*)d_in[2];
    const float* conv_w = (const float*)d_in[3];
    const float* conv_b = (const float*)d_in[4];
    const float* bn_g   = (const float*)d_in[5];
    const float* bn_b   = (const float*)d_in[6];
    const float* qkv_w  = (const float*)d_in[7];
    const float* fc_w   = (const float*)d_in[8];
    const float* fc_b   = (const float*)d_in[9];
    const float* w_out  = (const float*)d_in[10];
    const float* b_out  = (const float*)d_in[11];
    float* out = (float*)d_out;

    float *p_t, *p_bn, *p_qkv;
    uint32_t *p_hsp, *p_qsp, *p_asp;
    uint2 *p_cw, *p_qw, *p_fw, *p_wi, *p_wo;
    cudaGetSymbolAddress((void**)&p_t,   g_t);
    cudaGetSymbolAddress((void**)&p_bn,  g_bn);
    cudaGetSymbolAddress((void**)&p_qkv, g_qkv);
    cudaGetSymbolAddress((void**)&p_hsp, g_hsp);
    cudaGetSymbolAddress((void**)&p_qsp, g_qsp);
    cudaGetSymbolAddress((void**)&p_asp, g_asp);
    cudaGetSymbolAddress((void**)&p_cw,  g_cw);
    cudaGetSymbolAddress((void**)&p_qw,  g_qw);
    cudaGetSymbolAddress((void**)&p_fw,  g_fw);
    cudaGetSymbolAddress((void**)&p_wi,  g_wi);
    cudaGetSymbolAddress((void**)&p_wo,  g_wo);

    prep_all<<<(NC+NQ+NF+NI+NO + 255)/256, 256>>>(conv_w, qkv_w, fc_w, w_in, w_out);

    // input projection 64 -> 128, half2 output into g_hsp
    {
        dim3 g(HW/128, DIM/64, BATCH);
        gemm_f16<<<g, 256>>>(p_wi, x, 0, b_in, nullptr, p_hsp, 1, DIM, CIN);
    }

    for (int i = 0; i < DEPTH; i++) {
        const int d = 1 << i;
        {   // dilated conv
            dim3 g(2, HH, BATCH);
            conv3x3_f16<<<g, 256>>>(p_hsp, p_cw + (size_t)i*9*64*DIM,
                                    conv_b + i*DIM, p_t, d);
        }
        {   // bn + relu -> fp32 residual + half2 qkv input
            dim3 g((64*HW/4)/256, BATCH);
            bn_apply_relu<<<g, 256>>>(p_t, bn_g + i*DIM, bn_b + i*DIM, p_bn, p_qsp);
        }
        {   // qkv: 128 -> 384
            dim3 g(HW/128, (3*DIM)/64, BATCH);
            gemm_f16<<<g, 256>>>(p_qw + (size_t)i*64*3*DIM, p_qsp, 1, nullptr, nullptr,
                                 p_qkv, 0, 3*DIM, DIM);
        }
        {   // attention -> half2 att
            dim3 g(HW/32, HEADS, BATCH);
            dim3 blk(32, CH);
            attn_core<<<g, blk>>>(p_qkv, p_asp);
        }
        {   // fc + bias + residual -> half2 h
            dim3 g(HW/128, DIM/64, BATCH);
            gemm_f16<<<g, 256>>>(p_fw + (size_t)i*64*DIM, p_asp, 1, fc_b + i*DIM, p_bn,
                                 p_hsp, 1, DIM, DIM);
        }
    }

    // output projection 128 -> 64
    {
        dim3 g(HW/128, COUT/64, BATCH);
        gemm_f16<<<g, 256>>>(p_wo, p_hsp, 1, b_out, nullptr, out, 0, COUT, DIM);
    }
}

// round 12
// speedup vs baseline: 1.7390x; 1.0181x over previous
#include <cuda_runtime.h>
#include <cuda_fp16.h>
#include <cstdint>
#include <cstddef>

#define BATCH 2
#define DIM 128
#define CIN 64
#define COUT 64
#define HH 96
#define WW 96
#define HW (HH*WW)           // 9216
#define HEADS 8
#define CH 16
#define DEPTH 4
#define NIDX (BATCH*HH)      // 192 (b,y) slots for bn partials

// ---------------- scratch (device globals) ----------------
__device__ __align__(16) float g_t  [BATCH*DIM*HW];   // conv out (fp32, pre-BN)
__device__ __align__(16) float g_bn [BATCH*DIM*HW];   // bn+relu out (fp32 residual)
__device__ __align__(16) float g_qkv[BATCH*3*DIM*HW];
__device__ __align__(16) uint32_t g_hsp[BATCH*64*HW]; // half2 h
__device__ __align__(16) uint32_t g_qsp[BATCH*64*HW]; // half2 bn
__device__ __align__(16) uint32_t g_asp[BATCH*64*HW]; // half2 att
__device__ __align__(16) uint32_t g_xsp[BATCH*32*HW]; // half2 input x
__device__ float g_ps[DIM*NIDX];
__device__ float g_pq[DIM*NIDX];
// weights: exact fp16 split, SEPARATE hi/lo planes, layout [K/2][M]
#define NC (DEPTH*9*64*DIM)
#define NQ (DEPTH*64*3*DIM)
#define NF (DEPTH*64*DIM)
#define NI (32*DIM)
#define NO (64*COUT)
__device__ uint32_t g_cwh[NC], g_cwl[NC];
__device__ uint32_t g_qwh[NQ], g_qwl[NQ];
__device__ uint32_t g_fwh[NF], g_fwl[NF];
__device__ uint32_t g_wih[NI], g_wil[NI];
__device__ uint32_t g_woh[NO], g_wol[NO];

__device__ __forceinline__ uint32_t h2(float a, float b)
{
    __half2 h = __floats2half2_rn(a, b);
    return *reinterpret_cast<uint32_t*>(&h);
}
__device__ __forceinline__ void splitw(float x0, float x1, uint32_t& hi, uint32_t& lo)
{
    __half h0 = __float2half_rn(x0);
    __half h1 = __float2half_rn(x1);
    float l0 = x0 - __half2float(h0);
    float l1 = x1 - __half2float(h1);
    __half2 hh = __halves2half2(h0, h1);
    __half2 ll = __floats2half2_rn(l0, l1);
    hi = *reinterpret_cast<uint32_t*>(&hh);
    lo = *reinterpret_cast<uint32_t*>(&ll);
}

__device__ __forceinline__ void mma_f16(float c[4],
    uint32_t a0, uint32_t a1, uint32_t a2, uint32_t a3, uint32_t b0, uint32_t b1)
{
    asm volatile(
        "mma.sync.aligned.m16n8k16.row.col.f32.f16.f16.f32 "
        "{%0,%1,%2,%3}, {%4,%5,%6,%7}, {%8,%9}, {%0,%1,%2,%3};"
        : "+f"(c[0]), "+f"(c[1]), "+f"(c[2]), "+f"(c[3])
        : "r"(a0), "r"(a1), "r"(a2), "r"(a3), "r"(b0), "r"(b1));
}

__device__ __forceinline__ uint32_t smem_u32(const void* p) {
    uint32_t a;
    asm("{ .reg .u64 t; cvta.to.shared.u64 t, %1; cvt.u32.u64 %0, t; }" : "=r"(a) : "l"(p));
    return a;
}
__device__ __forceinline__ void cpa4(uint32_t saddr, const void* g, bool v) {
    asm volatile("cp.async.ca.shared.global [%0], [%1], 4, %2;"
        :: "r"(saddr), "l"(g), "r"(v ? 4u : 0u));
}
#define CP_COMMIT() asm volatile("cp.async.commit_group;" ::: "memory")
#define CP_WAIT2()  asm volatile("cp.async.wait_group 2;" ::: "memory")

// ---------------- weight prep (hi/lo planes) ----------------
__global__ void prep_all(const float* __restrict__ conv_w, const float* __restrict__ qkv_w,
                         const float* __restrict__ fc_w, const float* __restrict__ w_in,
                         const float* __restrict__ w_out)
{
    int i = blockIdx.x*256 + threadIdx.x;
    float x0, x1; uint32_t *dh, *dl;
    if (i < NC) {
        int oc = i & 127; int r = i >> 7; int ic2 = r & 63; r >>= 6;
        int tap = r % 9, d = r / 9;
        size_t base = ((size_t)(d*DIM + oc)*DIM + 2*ic2)*9 + tap;
        x0 = conv_w[base]; x1 = conv_w[base + 9]; dh = &g_cwh[i]; dl = &g_cwl[i];
    } else if (i < NC+NQ) {
        int j = i - NC; int d = j / (64*384); int l = j % (64*384);
        int k2 = l / 384, m = l % 384;
        x0 = qkv_w[((size_t)d*384 + m)*DIM + 2*k2];
        x1 = qkv_w[((size_t)d*384 + m)*DIM + 2*k2 + 1];
        dh = &g_qwh[j]; dl = &g_qwl[j];
    } else if (i < NC+NQ+NF) {
        int j = i - NC - NQ; int d = j / (64*DIM); int l = j % (64*DIM);
        int k2 = l / DIM, m = l % DIM;
        x0 = fc_w[((size_t)d*DIM + m)*DIM + 2*k2];
        x1 = fc_w[((size_t)d*DIM + m)*DIM + 2*k2 + 1];
        dh = &g_fwh[j]; dl = &g_fwl[j];
    } else if (i < NC+NQ+NF+NI) {
        int j = i - NC - NQ - NF; int k2 = j / DIM, m = j % DIM;
        x0 = w_in[(size_t)m*CIN + 2*k2]; x1 = w_in[(size_t)m*CIN + 2*k2 + 1];
        dh = &g_wih[j]; dl = &g_wil[j];
    } else if (i < NC+NQ+NF+NI+NO) {
        int j = i - NC - NQ - NF - NI; int k2 = j / COUT, m = j % COUT;
        x0 = w_out[(size_t)m*DIM + 2*k2]; x1 = w_out[(size_t)m*DIM + 2*k2 + 1];
        dh = &g_woh[j]; dl = &g_wol[j];
    } else return;
    uint32_t hi, lo; splitw(x0, x1, hi, lo);
    *dh = hi; *dl = lo;
}

// ---------------- split input x to half2 ----------------
__global__ void split_x(const float* __restrict__ X)
{
    int i = blockIdx.x*256 + threadIdx.x;
    if (i >= BATCH*32*HW) return;
    int p = i % HW; int r = i / HW; int k2 = r & 31; int b = r >> 5;
    float x0 = X[((size_t)b*CIN + 2*k2)*HW + p];
    float x1 = X[((size_t)b*CIN + 2*k2 + 1)*HW + p];
    g_xsp[(size_t)b*32*HW + (size_t)k2*HW + p] = h2(x0, x1);
}

// ---------------- fp16x2 GEMM (4-stage cp.async, 64m x 128n) ----------------
// Wh/Wl: [K/2][Mtot] half2 planes. B: half2 [K/2][HW].
// Out: fp32 [Mtot][HW] (osplit=0) or half2 [Mtot/2][HW] (osplit=1).
__global__ void gemm_f16(const uint32_t* __restrict__ Wh, const uint32_t* __restrict__ Wl,
                         const uint32_t* __restrict__ Bin,
                         const float* __restrict__ bias, const float* __restrict__ res,
                         void* __restrict__ Out, int osplit, int Mtot, int K)
{
    const int b  = blockIdx.z;
    const int m0 = blockIdx.y * 64, n0 = blockIdx.x * 128;

    __shared__ uint32_t As[4][2][8][72];
    __shared__ uint32_t Bs[4][8][136];

    const int tid  = threadIdx.x;
    const int warp = tid >> 5, lane = tid & 31;
    const int wm = warp >> 2, wn = warp & 3;
    const int g = lane >> 2, t = lane & 3;
    const int tt0 = tid >> 6, mcol = tid & 63;

    const uint32_t sA = smem_u32(As), sB = smem_u32(Bs);
    const uint32_t* Bsp = Bin + (size_t)b*(K/2)*HW;
    const int nk = K/16;
    float acc[2][4][4] = {};

#define G_ISSUE(c) do { \
        int s_ = (c) & 3; \
        uint32_t a0_ = sA + (((s_*2+0)*8 + tt0)*72 + mcol)*4; \
        uint32_t a1_ = sA + (((s_*2+1)*8 + tt0)*72 + mcol)*4; \
        cpa4(a0_,        &Wh[(size_t)((c)*8 + tt0)*Mtot + m0 + mcol], true); \
        cpa4(a0_ + 4*288,&Wh[(size_t)((c)*8 + tt0 + 4)*Mtot + m0 + mcol], true); \
        cpa4(a1_,        &Wl[(size_t)((c)*8 + tt0)*Mtot + m0 + mcol], true); \
        cpa4(a1_ + 4*288,&Wl[(size_t)((c)*8 + tt0 + 4)*Mtot + m0 + mcol], true); \
        _Pragma("unroll") \
        for (int j_ = 0; j_ < 4; j_++) { \
            int i_ = tid + j_*256; int tt_ = i_ >> 7; int n_ = i_ & 127; \
            cpa4(sB + ((s_*8 + tt_)*136 + n_)*4, \
                 &Bsp[(size_t)((c)*8 + tt_)*HW + n0 + n_], true); \
        } \
    } while(0)

    G_ISSUE(0); CP_COMMIT();
    G_ISSUE(1); CP_COMMIT();
    G_ISSUE(2); CP_COMMIT();
    for (int c = 0; c < nk; c++) {
        const int cur = c & 3;
        CP_WAIT2();
        __syncthreads();

        uint32_t ah[2][4], al[2][4];
        #pragma unroll
        for (int mt = 0; mt < 2; mt++) {
            int mrow = wm*32 + mt*16 + g;
            ah[mt][0] = As[cur][0][t  ][mrow]; ah[mt][1] = As[cur][0][t  ][mrow+8];
            ah[mt][2] = As[cur][0][t+4][mrow]; ah[mt][3] = As[cur][0][t+4][mrow+8];
            al[mt][0] = As[cur][1][t  ][mrow]; al[mt][1] = As[cur][1][t  ][mrow+8];
            al[mt][2] = As[cur][1][t+4][mrow]; al[mt][3] = As[cur][1][t+4][mrow+8];
        }
        #pragma unroll
        for (int nt = 0; nt < 4; nt++) {
            int col = wn*32 + nt*8 + g;
            uint32_t b0 = Bs[cur][t][col], b1 = Bs[cur][t+4][col];
            #pragma unroll
            for (int mt = 0; mt < 2; mt++) {
                mma_f16(acc[mt][nt], ah[mt][0], ah[mt][1], ah[mt][2], ah[mt][3], b0, b1);
                mma_f16(acc[mt][nt], al[mt][0], al[mt][1], al[mt][2], al[mt][3], b0, b1);
            }
        }
        if (c + 3 < nk) G_ISSUE(c + 3);
        CP_COMMIT();
    }
#undef G_ISSUE

    const float* Rb = res ? res + (size_t)b*Mtot*HW : nullptr;

    #pragma unroll
    for (int mt = 0; mt < 2; mt++) {
        const int row0 = m0 + wm*32 + mt*16 + g;
        const float b0v = bias ? bias[row0]     : 0.f;
        const float b1v = bias ? bias[row0 + 8] : 0.f;
        #pragma unroll
        for (int nt = 0; nt < 4; nt++) {
            int col = n0 + wn*32 + nt*8 + 2*t;
            float v00 = acc[mt][nt][0] + b0v, v01 = acc[mt][nt][1] + b0v;
            float v10 = acc[mt][nt][2] + b1v, v11 = acc[mt][nt][3] + b1v;
            if (Rb) {
                float2 r0 = *(const float2*)&Rb[(size_t)row0*HW + col];
                float2 r1 = *(const float2*)&Rb[(size_t)(row0+8)*HW + col];
                v00 += r0.x; v01 += r0.y; v10 += r1.x; v11 += r1.y;
            }
            if (!osplit) {
                float* Yb = (float*)Out + (size_t)b*Mtot*HW;
                *(float2*)&Yb[(size_t)row0*HW + col]     = make_float2(v00, v01);
                *(float2*)&Yb[(size_t)(row0+8)*HW + col] = make_float2(v10, v11);
            } else {
                float p00 = __shfl_xor_sync(0xffffffffu, v00, 4);
                float p01 = __shfl_xor_sync(0xffffffffu, v01, 4);
                float p10 = __shfl_xor_sync(0xffffffffu, v10, 4);
                float p11 = __shfl_xor_sync(0xffffffffu, v11, 4);
                if (!(g & 1)) {
                    uint32_t* Osp = (uint32_t*)Out + (size_t)b*64*HW;
                    int c2 = row0 >> 1;
                    *(uint2*)&Osp[(size_t)c2*HW + col]     = make_uint2(h2(v00,p00), h2(v01,p01));
                    *(uint2*)&Osp[(size_t)(c2+4)*HW + col] = make_uint2(h2(v10,p10), h2(v11,p11));
                }
            }
        }
    }
}

// ---------------- dilated 3x3 conv (fp16x2, 4-stage cp.async, 64m x 96n) ----------------
__global__ void conv3x3_f16(const uint32_t* __restrict__ Bsp,
                            const uint32_t* __restrict__ CWh, const uint32_t* __restrict__ CWl,
                            const float* __restrict__ bias, float* __restrict__ Y, int d)
{
    const int m0 = blockIdx.x * 64;
    const int y  = blockIdx.y;
    const int b  = blockIdx.z;
    const uint32_t* Xb = Bsp + (size_t)b*64*HW;

    __shared__ uint32_t As[4][2][8][72];
    __shared__ uint32_t Bs[4][8][104];
    __shared__ float sS[2][64], sQ[2][64];

    const int tid  = threadIdx.x;
    const int warp = tid >> 5, lane = tid & 31;
    const int wm = warp >> 1, wn = warp & 1;
    const int g = lane >> 2, t = lane & 3;
    const int tt0 = tid >> 6, mcol = tid & 63;

    const uint32_t sA = smem_u32(As), sB = smem_u32(Bs);

    int tidx[9], txs[9], roff[9], nv = 0;
    #pragma unroll
    for (int tap = 0; tap < 9; tap++) {
        int dy = tap/3 - 1, dx = tap%3 - 1;
        int yy = y + dy*d;
        if (yy >= 0 && yy < HH) {
            tidx[nv] = tap; txs[nv] = dx*d; roff[nv] = yy*WW; nv++;
        }
    }
    const int nchunks = nv * 8;

    float acc[6][4] = {};

#define C_ISSUE(cc) do { \
        int tv_ = (cc) >> 3, kc_ = (cc) & 7; int icb_ = kc_*8; int s_ = (cc) & 3; \
        const uint32_t* Wh_ = CWh + (size_t)tidx[tv_]*64*DIM; \
        const uint32_t* Wl_ = CWl + (size_t)tidx[tv_]*64*DIM; \
        uint32_t a0_ = sA + (((s_*2+0)*8 + tt0)*72 + mcol)*4; \
        uint32_t a1_ = sA + (((s_*2+1)*8 + tt0)*72 + mcol)*4; \
        cpa4(a0_,         &Wh_[(size_t)(icb_ + tt0)*DIM + m0 + mcol], true); \
        cpa4(a0_ + 4*288, &Wh_[(size_t)(icb_ + tt0 + 4)*DIM + m0 + mcol], true); \
        cpa4(a1_,         &Wl_[(size_t)(icb_ + tt0)*DIM + m0 + mcol], true); \
        cpa4(a1_ + 4*288, &Wl_[(size_t)(icb_ + tt0 + 4)*DIM + m0 + mcol], true); \
        const uint32_t* Xr_ = Xb + roff[tv_]; int sh_ = txs[tv_]; \
        _Pragma("unroll") \
        for (int j_ = 0; j_ < 3; j_++) { \
            int i_ = tid + j_*256; int tt_ = i_ / 96; int n_ = i_ - 96*tt_; \
            int xx_ = n_ + sh_; \
            bool v_ = (xx_ >= 0 && xx_ < WW); \
            int xc_ = v_ ? xx_ : 0; \
            cpa4(sB + ((s_*8 + tt_)*104 + n_)*4, \
                 &Xr_[(size_t)(icb_ + tt_)*HW + xc_], v_); \
        } \
    } while(0)

    C_ISSUE(0); CP_COMMIT();
    C_ISSUE(1); CP_COMMIT();
    C_ISSUE(2); CP_COMMIT();
    for (int cc = 0; cc < nchunks; cc++) {
        const int cur = cc & 3;
        CP_WAIT2();
        __syncthreads();

        const int mrow = wm*16 + g;
        uint32_t ah0 = As[cur][0][t  ][mrow], ah1 = As[cur][0][t  ][mrow+8];
        uint32_t ah2 = As[cur][0][t+4][mrow], ah3 = As[cur][0][t+4][mrow+8];
        uint32_t al0 = As[cur][1][t  ][mrow], al1 = As[cur][1][t  ][mrow+8];
        uint32_t al2 = As[cur][1][t+4][mrow], al3 = As[cur][1][t+4][mrow+8];
        #pragma unroll
        for (int nt = 0; nt < 6; nt++) {
            int col = wn*48 + nt*8 + g;
            uint32_t b0 = Bs[cur][t][col], b1 = Bs[cur][t+4][col];
            mma_f16(acc[nt], ah0, ah1, ah2, ah3, b0, b1);
            mma_f16(acc[nt], al0, al1, al2, al3, b0, b1);
        }
        if (cc + 3 < nchunks) C_ISSUE(cc + 3);
        CP_COMMIT();
    }
#undef C_ISSUE

    float* Yb = Y + (size_t)b*DIM*HW + (size_t)y*WW;
    const int row0 = m0 + wm*16 + g;
    const float b0v = bias[row0], b1v = bias[row0 + 8];
    float s0 = 0.f, q0 = 0.f, s1 = 0.f, q1 = 0.f;
    #pragma unroll
    for (int nt = 0; nt < 6; nt++) {
        int col = wn*48 + nt*8 + 2*t;
        float v00 = acc[nt][0] + b0v, v01 = acc[nt][1] + b0v;
        float v10 = acc[nt][2] + b1v, v11 = acc[nt][3] + b1v;
        *(float2*)&Yb[(size_t)row0*HW + col]     = make_float2(v00, v01);
        *(float2*)&Yb[(size_t)(row0+8)*HW + col] = make_float2(v10, v11);
        s0 += v00 + v01; q0 += v00*v00 + v01*v01;
        s1 += v10 + v11; q1 += v10*v10 + v11*v11;
    }
    #pragma unroll
    for (int o = 1; o <= 2; o <<= 1) {
        s0 += __shfl_xor_sync(0xffffffffu, s0, o);
        q0 += __shfl_xor_sync(0xffffffffu, q0, o);
        s1 += __shfl_xor_sync(0xffffffffu, s1, o);
        q1 += __shfl_xor_sync(0xffffffffu, q1, o);
    }
    if (t == 0) {
        int lr = wm*16 + g;
        sS[wn][lr] = s0;   sQ[wn][lr] = q0;
        sS[wn][lr+8] = s1; sQ[wn][lr+8] = q1;
    }
    __syncthreads();
    if (tid < 64) {
        int idx = b*HH + y;
        g_ps[(size_t)(m0+tid)*NIDX + idx] = sS[0][tid] + sS[1][tid];
        g_pq[(size_t)(m0+tid)*NIDX + idx] = sQ[0][tid] + sQ[1][tid];
    }
}

// ---------------- bn apply + relu (inline stats) ----------------
__global__ void bn_apply_relu(const float* __restrict__ X, const float* __restrict__ gam,
                              const float* __restrict__ beta, float* __restrict__ Yf,
                              uint32_t* __restrict__ Ysp)
{
    const int b = blockIdx.y;
    int i = blockIdx.x*256 + threadIdx.x;
    int c2 = i / (HW/4);
    int p  = (i - c2*(HW/4)) * 4;
    int c0 = 2*c2, c1 = 2*c2 + 1;

    __shared__ float st[4];
    __shared__ float rs[4][8];
    {
        float s0=0.f, q0=0.f, s1=0.f, q1=0.f;
        int tt = threadIdx.x;
        if (tt < NIDX) {
            s0 = g_ps[(size_t)c0*NIDX + tt]; q0 = g_pq[(size_t)c0*NIDX + tt];
            s1 = g_ps[(size_t)c1*NIDX + tt]; q1 = g_pq[(size_t)c1*NIDX + tt];
        }
        #pragma unroll
        for (int o = 16; o > 0; o >>= 1) {
            s0 += __shfl_xor_sync(0xffffffffu, s0, o);
            q0 += __shfl_xor_sync(0xffffffffu, q0, o);
            s1 += __shfl_xor_sync(0xffffffffu, s1, o);
            q1 += __shfl_xor_sync(0xffffffffu, q1, o);
        }
        int w = threadIdx.x >> 5;
        if ((threadIdx.x & 31) == 0) {
            rs[0][w] = s0; rs[1][w] = q0; rs[2][w] = s1; rs[3][w] = q1;
        }
        __syncthreads();
        if (threadIdx.x == 0) {
            float S0=0,Q0=0,S1=0,Q1=0;
            #pragma unroll
            for (int k = 0; k < 8; k++) { S0+=rs[0][k]; Q0+=rs[1][k]; S1+=rs[2][k]; Q1+=rs[3][k]; }
            const float invN = 1.f / (BATCH*HW);
            float mm0 = S0*invN, mm1 = S1*invN;
            st[0] = mm0; st[1] = rsqrtf(Q0*invN - mm0*mm0 + 1e-5f);
            st[2] = mm1; st[3] = rsqrtf(Q1*invN - mm1*mm1 + 1e-5f);
        }
        __syncthreads();
    }
    float m0 = st[0], r0 = st[1], m1 = st[2], r1 = st[3];
    float ga0 = gam[c0], be0 = beta[c0], ga1 = gam[c1], be1 = beta[c1];

    const float* Xb = X + (size_t)b*DIM*HW;
    float* Yb = Yf + (size_t)b*DIM*HW;
    uint32_t* Sb = Ysp + (size_t)b*64*HW;

    float4 a = *(const float4*)&Xb[(size_t)c0*HW + p];
    float4 c = *(const float4*)&Xb[(size_t)c1*HW + p];
    float y0x = fmaxf((a.x-m0)*r0*ga0+be0, 0.f), y0y = fmaxf((a.y-m0)*r0*ga0+be0, 0.f);
    float y0z = fmaxf((a.z-m0)*r0*ga0+be0, 0.f), y0w = fmaxf((a.w-m0)*r0*ga0+be0, 0.f);
    float y1x = fmaxf((c.x-m1)*r1*ga1+be1, 0.f), y1y = fmaxf((c.y-m1)*r1*ga1+be1, 0.f);
    float y1z = fmaxf((c.z-m1)*r1*ga1+be1, 0.f), y1w = fmaxf((c.w-m1)*r1*ga1+be1, 0.f);

    *(float4*)&Yb[(size_t)c0*HW + p] = make_float4(y0x, y0y, y0z, y0w);
    *(float4*)&Yb[(size_t)c1*HW + p] = make_float4(y1x, y1y, y1z, y1w);

    *(uint4*)&Sb[(size_t)c2*HW + p] =
        make_uint4(h2(y0x, y1x), h2(y0y, y1y), h2(y0z, y1z), h2(y0w, y1w));
}

// ---------------- local channel self-attention (half2 epilogue) ----------------
__global__ void attn_core(const float* __restrict__ QKV, uint32_t* __restrict__ OUT)
{
    const int b = blockIdx.z, h = blockIdx.y;
    const int p0 = blockIdx.x * 32;
    const int y  = p0 / WW, x0 = p0 % WW;
    const float* Qb = QKV + ((size_t)b*3*DIM + h*CH)*HW;
    const float* Kb = Qb + (size_t)DIM*HW;
    const float* Vb = Qb + (size_t)2*DIM*HW;

    __shared__ float qs[CH][3][34];
    __shared__ float ks[CH][3][34];
    __shared__ float vs[CH][3][34];
    __shared__ float sato[CH][33];

    const int tid = threadIdx.y*32 + threadIdx.x;
    for (int i = tid; i < CH*3*34; i += 512) {
        int xi = i % 34; int rr = i / 34; int yi = rr % 3; int c = rr / 3;
        int yy = y + yi - 1, xx = x0 + xi - 1;
        bool ok = (yy >= 0 && yy < HH && xx >= 0 && xx < WW);
        int o = c*HW + yy*WW + xx;
        qs[c][yi][xi] = ok ? Qb[o] : 0.f;
        ks[c][yi][xi] = ok ? Kb[o] : 0.f;
        vs[c][yi][xi] = ok ? Vb[o] : 0.f;
    }
    __syncthreads();

    const int nn = threadIdx.y, lx = threadIdx.x;
    float qr[9];
    #pragma unroll
    for (int t = 0; t < 9; t++) qr[t] = qs[nn][t/3][lx + t%3] * 0.25f;

    float dots[CH], vsum[CH];
    #pragma unroll
    for (int m = 0; m < CH; m++) {
        float dv = 0.f, sv = 0.f;
        #pragma unroll
        for (int t = 0; t < 9; t++) {
            dv += qr[t] * ks[m][t/3][lx + t%3];
            sv += vs[m][t/3][lx + t%3];
        }
        dots[m] = dv; vsum[m] = sv;
    }
    float mx = dots[0];
    #pragma unroll
    for (int m = 1; m < CH; m++) mx = fmaxf(mx, dots[m]);
    float s = 0.f;
    #pragma unroll
    for (int m = 0; m < CH; m++) { dots[m] = __expf(dots[m]-mx); s += dots[m]; }
    float o = 0.f;
    #pragma unroll
    for (int m = 0; m < CH; m++) o += dots[m]*vsum[m];
    sato[nn][lx] = o / s;
    __syncthreads();

    if (nn < 8) {
        float v0 = sato[2*nn][lx], v1 = sato[2*nn+1][lx];
        OUT[(size_t)b*64*HW + (size_t)(h*8 + nn)*HW + p0 + lx] = h2(v0, v1);
    }
}

// ---------------- host orchestration ----------------
extern "C" void kernel_launch(void* const* d_in, const int* in_sizes, int n_in,
                              void* d_out, int out_size)
{
    const float* x      = (const float*)d_in[0];
    const float* w_in   = (const float*)d_in[1];
    const float* b_in   = (const float*)d_in[2];
    const float* conv_w = (const float*)d_in[3];
    const float* conv_b = (const float*)d_in[4];
    const float* bn_g   = (const float*)d_in[5];
    const float* bn_b   = (const float*)d_in[6];
    const float* qkv_w  = (const float*)d_in[7];
    const float* fc_w   = (const float*)d_in[8];
    const float* fc_b   = (const float*)d_in[9];
    const float* w_out  = (const float*)d_in[10];
    const float* b_out  = (const float*)d_in[11];
    float* out = (float*)d_out;

    float *p_t, *p_bn, *p_qkv;
    uint32_t *p_hsp, *p_qsp, *p_asp, *p_xsp;
    uint32_t *p_cwh, *p_cwl, *p_qwh, *p_qwl, *p_fwh, *p_fwl, *p_wih, *p_wil, *p_woh, *p_wol;
    cudaGetSymbolAddress((void**)&p_t,   g_t);
    cudaGetSymbolAddress((void**)&p_bn,  g_bn);
    cudaGetSymbolAddress((void**)&p_qkv, g_qkv);
    cudaGetSymbolAddress((void**)&p_hsp, g_hsp);
    cudaGetSymbolAddress((void**)&p_qsp, g_qsp);
    cudaGetSymbolAddress((void**)&p_asp, g_asp);
    cudaGetSymbolAddress((void**)&p_xsp, g_xsp);
    cudaGetSymbolAddress((void**)&p_cwh, g_cwh);
    cudaGetSymbolAddress((void**)&p_cwl, g_cwl);
    cudaGetSymbolAddress((void**)&p_qwh, g_qwh);
    cudaGetSymbolAddress((void**)&p_qwl, g_qwl);
    cudaGetSymbolAddress((void**)&p_fwh, g_fwh);
    cudaGetSymbolAddress((void**)&p_fwl, g_fwl);
    cudaGetSymbolAddress((void**)&p_wih, g_wih);
    cudaGetSymbolAddress((void**)&p_wil, g_wil);
    cudaGetSymbolAddress((void**)&p_woh, g_woh);
    cudaGetSymbolAddress((void**)&p_wol, g_wol);

    prep_all<<<(NC+NQ+NF+NI+NO + 255)/256, 256>>>(conv_w, qkv_w, fc_w, w_in, w_out);
    split_x<<<(BATCH*32*HW + 255)/256, 256>>>(x);

    // input projection 64 -> 128, half2 output into g_hsp
    {
        dim3 g(HW/128, DIM/64, BATCH);
        gemm_f16<<<g, 256>>>(p_wih, p_wil, p_xsp, b_in, nullptr, p_hsp, 1, DIM, CIN);
    }

    for (int i = 0; i < DEPTH; i++) {
        const int d = 1 << i;
        {   // dilated conv
            dim3 g(2, HH, BATCH);
            conv3x3_f16<<<g, 256>>>(p_hsp, p_cwh + (size_t)i*9*64*DIM,
                                    p_cwl + (size_t)i*9*64*DIM, conv_b + i*DIM, p_t, d);
        }
        {   // bn + relu -> fp32 residual + half2 qkv input
            dim3 g((64*HW/4)/256, BATCH);
            bn_apply_relu<<<g, 256>>>(p_t, bn_g + i*DIM, bn_b + i*DIM, p_bn, p_qsp);
        }
        {   // qkv: 128 -> 384
            dim3 g(HW/128, (3*DIM)/64, BATCH);
            gemm_f16<<<g, 256>>>(p_qwh + (size_t)i*64*3*DIM, p_qwl + (size_t)i*64*3*DIM,
                                 p_qsp, nullptr, nullptr, p_qkv, 0, 3*DIM, DIM);
        }
        {   // attention -> half2 att
            dim3 g(HW/32, HEADS, BATCH);
            dim3 blk(32, CH);
            attn_core<<<g, blk>>>(p_qkv, p_asp);
        }
        {   // fc + bias + residual -> half2 h
            dim3 g(HW/128, DIM/64, BATCH);
            gemm_f16<<<g, 256>>>(p_fwh + (size_t)i*64*DIM, p_fwl + (size_t)i*64*DIM,
                                 p_asp, fc_b + i*DIM, p_bn, p_hsp, 1, DIM, DIM);
        }
    }

    // output projection 128 -> 64
    {
        dim3 g(HW/128, COUT/64, BATCH);
        gemm_f16<<<g, 256>>>(p_woh, p_wol, p_hsp, b_out, nullptr, out, 0, COUT, DIM);
    }
}